// round 14
// baseline (speedup 1.0000x reference)
#include <cuda_runtime.h>
#include <cuda_bf16.h>
#include <cuda_fp16.h>
#include <math.h>
#include <stdint.h>

#define LSEQ 2048
#define DI   2048
#define DM   1024
#define E2   4096
#define NST  16
#define NBT  32

// ---------------- scratch ----------------
__device__ float  g_xz[33554432];    // [4][4096][2048]
__device__ float  g_xc[16777216];    // [4][2048][2048]
__device__ float  g_xdbl[786432];    // [4][96][2048]
__device__ float  g_delta[16777216]; // [4][2048][2048]
__device__ float  g_feat[65536];     // [32][2048]
__device__ float  g_A[32768];        // [2048][16]
__device__ __half g_hh[8388608];     // fp16 hidden
__device__ __half g_w1h[4194304];    // fp16 in_proj_w
__device__ __half g_woh[2097152];    // fp16 out_proj_w
__device__ __half g_yh[16777216];    // fp16 y (l,d)

__device__ __forceinline__ float softplus_f(float x) {
    return fmaxf(x, 0.f) + log1pf(expf(-fabsf(x)));
}

__device__ __forceinline__ uint32_t f2tf(float f) {
    uint32_t r;
    asm("cvt.rna.tf32.f32 %0, %1;" : "=r"(r) : "f"(f));
    return r;
}

__device__ __forceinline__ void mma_tf32(float c[4], const uint32_t a[4], const uint32_t b[2]) {
    asm volatile(
        "mma.sync.aligned.m16n8k8.row.col.f32.tf32.tf32.f32 "
        "{%0,%1,%2,%3}, {%4,%5,%6,%7}, {%8,%9}, {%0,%1,%2,%3};\n"
        : "+f"(c[0]), "+f"(c[1]), "+f"(c[2]), "+f"(c[3])
        : "r"(a[0]), "r"(a[1]), "r"(a[2]), "r"(a[3]), "r"(b[0]), "r"(b[1]));
}

__device__ __forceinline__ void mma_f16(float c[4], const uint32_t a[4], const uint32_t b[2]) {
    asm volatile(
        "mma.sync.aligned.m16n8k16.row.col.f32.f16.f16.f32 "
        "{%0,%1,%2,%3}, {%4,%5,%6,%7}, {%8,%9}, {%0,%1,%2,%3};\n"
        : "+f"(c[0]), "+f"(c[1]), "+f"(c[2]), "+f"(c[3])
        : "r"(a[0]), "r"(a[1]), "r"(a[2]), "r"(a[3]), "r"(b[0]), "r"(b[1]));
}

__device__ __forceinline__ void ldm_x4(uint32_t r[4], uint32_t addr) {
    asm volatile("ldmatrix.sync.aligned.m8n8.x4.shared.b16 {%0,%1,%2,%3}, [%4];"
        : "=r"(r[0]), "=r"(r[1]), "=r"(r[2]), "=r"(r[3]) : "r"(addr));
}

__device__ __forceinline__ void cp_async16(uint32_t smem_addr, const void* gptr) {
    asm volatile("cp.async.cg.shared.global [%0], [%1], 16;\n" :: "r"(smem_addr), "l"(gptr));
}
__device__ __forceinline__ void cp_commit() {
    asm volatile("cp.async.commit_group;\n");
}
template<int N>
__device__ __forceinline__ void cp_wait() {
    asm volatile("cp.async.wait_group %0;\n" :: "n"(N));
}

__device__ __forceinline__ float blockReduceSum256(float v, float* red, int tid) {
    #pragma unroll
    for (int o = 16; o > 0; o >>= 1) v += __shfl_xor_sync(0xffffffffu, v, o);
    if ((tid & 31) == 0) red[tid >> 5] = v;
    __syncthreads();
    if (tid < 8) {
        float r = red[tid];
        #pragma unroll
        for (int o = 4; o > 0; o >>= 1) r += __shfl_xor_sync(0xffu, r, o);
        if (tid == 0) red[32] = r;
    }
    __syncthreads();
    float out = red[32];
    __syncthreads();
    return out;
}

__device__ __forceinline__ float blockReduceMax256(float v, float* red, int tid) {
    #pragma unroll
    for (int o = 16; o > 0; o >>= 1) v = fmaxf(v, __shfl_xor_sync(0xffffffffu, v, o));
    if ((tid & 31) == 0) red[tid >> 5] = v;
    __syncthreads();
    if (tid < 8) {
        float r = red[tid];
        #pragma unroll
        for (int o = 4; o > 0; o >>= 1) r = fmaxf(r, __shfl_xor_sync(0xffu, r, o));
        if (tid == 0) red[32] = r;
    }
    __syncthreads();
    float out = red[32];
    __syncthreads();
    return out;
}

// ---------------- f32 -> f16 conversion (8 elems / thread) ----------------
__global__ void __launch_bounds__(256) f32_to_f16_kernel(const float* __restrict__ in,
                                                         __half* __restrict__ out, int n8) {
    int i = blockIdx.x * 256 + threadIdx.x;
    if (i < n8) {
        float4 a = ((const float4*)in)[2 * i];
        float4 b = ((const float4*)in)[2 * i + 1];
        __half2 h0 = __floats2half2_rn(a.x, a.y);
        __half2 h1 = __floats2half2_rn(a.z, a.w);
        __half2 h2 = __floats2half2_rn(b.x, b.y);
        __half2 h3 = __floats2half2_rn(b.z, b.w);
        uint4 r;
        r.x = *(uint32_t*)&h0; r.y = *(uint32_t*)&h1;
        r.z = *(uint32_t*)&h2; r.w = *(uint32_t*)&h3;
        ((uint4*)out)[i] = r;
    }
}

// =====================================================================
// FP16 NT GEMM: C[M,N]=A(MxK)*B(NxK)^T, fp32 accum.
// =====================================================================
#define HPITCH 72
#define HTSZ (128 * HPITCH)
#define HSTAGES 3

__global__ void __launch_bounds__(256, 2) hgemm_nt(const __half* __restrict__ Ag,
                                                   const __half* __restrict__ Bg,
                                                   float* __restrict__ Cg,
                                                   int M, int N, int K,
                                                   long long sA, long long sB, long long sC) {
    extern __shared__ __half hsm[];
    const __half* A = Ag + (long long)blockIdx.z * sA;
    const __half* B = Bg + (long long)blockIdx.z * sB;
    float*        C = Cg + (long long)blockIdx.z * sC;
    const int m0 = blockIdx.y * 128, n0 = blockIdx.x * 128;

    const int tid = threadIdx.x;
    const int wid = tid >> 5, lane = tid & 31;
    const int wm = (wid >> 2) * 64;
    const int wn = (wid & 3) * 32;
    const int g = lane >> 2, tg = lane & 3;
    const int r8 = lane & 7, q = lane >> 3;

    const int nk = K >> 6;

    auto issue_tile = [&](int s, int kt) {
        if (kt < nk) {
            int k0 = kt << 6;
            __half* As = hsm + s * 2 * HTSZ;
            __half* Bs = As + HTSZ;
            #pragma unroll
            for (int r = 0; r < 4; r++) {
                int c = tid + r * 256;
                int row = c >> 3;
                int kq = (c & 7) << 3;
                uint32_t dst = (uint32_t)__cvta_generic_to_shared(As + row * HPITCH + kq);
                cp_async16(dst, A + (long long)(m0 + row) * K + k0 + kq);
            }
            #pragma unroll
            for (int r = 0; r < 4; r++) {
                int c = tid + r * 256;
                int row = c >> 3;
                int kq = (c & 7) << 3;
                uint32_t dst = (uint32_t)__cvta_generic_to_shared(Bs + row * HPITCH + kq);
                cp_async16(dst, B + (long long)(n0 + row) * K + k0 + kq);
            }
        }
        cp_commit();
    };

    float c[4][4][4];
    #pragma unroll
    for (int mi = 0; mi < 4; mi++)
        #pragma unroll
        for (int ni = 0; ni < 4; ni++)
            #pragma unroll
            for (int r = 0; r < 4; r++) c[mi][ni][r] = 0.f;

    issue_tile(0, 0);
    issue_tile(1, 1);

    for (int kt = 0; kt < nk; kt++) {
        issue_tile((kt + 2) % HSTAGES, kt + 2);
        cp_wait<2>();
        __syncthreads();
        const __half* As = hsm + (kt % HSTAGES) * 2 * HTSZ;
        const __half* Bs = As + HTSZ;

        #pragma unroll
        for (int kk = 0; kk < 64; kk += 16) {
            uint32_t a[4][4], bfr[4][2];
            #pragma unroll
            for (int mi = 0; mi < 4; mi++) {
                const __half* ap = As + (wm + mi * 16 + ((q & 1) << 3) + r8) * HPITCH
                                      + kk + ((q >> 1) << 3);
                ldm_x4(a[mi], (uint32_t)__cvta_generic_to_shared(ap));
            }
            #pragma unroll
            for (int nn = 0; nn < 2; nn++) {
                uint32_t bt[4];
                const __half* bp = Bs + (wn + nn * 16 + ((q >> 1) << 3) + r8) * HPITCH
                                      + kk + ((q & 1) << 3);
                ldm_x4(bt, (uint32_t)__cvta_generic_to_shared(bp));
                bfr[2 * nn][0] = bt[0];     bfr[2 * nn][1] = bt[1];
                bfr[2 * nn + 1][0] = bt[2]; bfr[2 * nn + 1][1] = bt[3];
            }
            #pragma unroll
            for (int mi = 0; mi < 4; mi++)
                #pragma unroll
                for (int ni = 0; ni < 4; ni++)
                    mma_f16(c[mi][ni], a[mi], bfr[ni]);
        }
        __syncthreads();
    }

    #pragma unroll
    for (int mi = 0; mi < 4; mi++) {
        int r0 = m0 + wm + mi * 16 + g;
        int r1 = r0 + 8;
        #pragma unroll
        for (int ni = 0; ni < 4; ni++) {
            int col = n0 + wn + ni * 8 + 2 * tg;
            *(float2*)(C + (long long)r0 * N + col) = make_float2(c[mi][ni][0], c[mi][ni][1]);
            *(float2*)(C + (long long)r1 * N + col) = make_float2(c[mi][ni][2], c[mi][ni][3]);
        }
    }
}
#define HSMEM (HSTAGES * 2 * HTSZ * 2)

// =====================================================================
// TF32 NN GEMM (small): C[M,N]=A(MxK)*B(KxN); EPI=1: softplus(+bias)
// =====================================================================
#define APITCH 36
#define BPITCH_NN 136
#define ASZ (128 * APITCH)
#define BSZ_N (32 * BPITCH_NN)
#define STAGES 3

template<int EPI>
__global__ void __launch_bounds__(256, 2) tc_gemm_nn(const float* __restrict__ Ag,
                                                     const float* __restrict__ Bg,
                                                     float* __restrict__ Cg,
                                                     int M, int N, int K,
                                                     long long sA, long long sB, long long sC,
                                                     const float* __restrict__ bias) {
    extern __shared__ float smem[];
    float* AsBase = smem;
    float* BsBase = smem + STAGES * ASZ;

    const float* A = Ag + (long long)blockIdx.z * sA;
    const float* B = Bg + (long long)blockIdx.z * sB;
    float*       C = Cg + (long long)blockIdx.z * sC;
    const int m0 = blockIdx.y * 128, n0 = blockIdx.x * 128;

    const int tid = threadIdx.x;
    const int wid = tid >> 5, lane = tid & 31;
    const int wm = (wid >> 2) * 64;
    const int wn = (wid & 3) * 32;
    const int g = lane >> 2, tg = lane & 3;

    const int nk = K >> 5;

    auto issue_tile = [&](int s, int kt) {
        if (kt < nk) {
            int k0 = kt << 5;
            float* As = AsBase + s * ASZ;
            float* Bs = BsBase + s * BSZ_N;
            #pragma unroll
            for (int r = 0; r < 4; r++) {
                int c = tid + r * 256;
                int row = c >> 3;
                int kq = (c & 7) << 2;
                int mrow = m0 + row;
                if (mrow >= M) mrow = M - 1;
                uint32_t dst = (uint32_t)__cvta_generic_to_shared(As + row * APITCH + kq);
                cp_async16(dst, A + (long long)mrow * K + k0 + kq);
            }
            #pragma unroll
            for (int r = 0; r < 4; r++) {
                int c = tid + r * 256;
                int k = c >> 5;
                int nq = (c & 31) << 2;
                uint32_t dst = (uint32_t)__cvta_generic_to_shared(Bs + k * BPITCH_NN + nq);
                cp_async16(dst, B + (long long)(k0 + k) * N + n0 + nq);
            }
        }
        cp_commit();
    };

    float c[4][4][4];
    #pragma unroll
    for (int mi = 0; mi < 4; mi++)
        #pragma unroll
        for (int ni = 0; ni < 4; ni++)
            #pragma unroll
            for (int r = 0; r < 4; r++) c[mi][ni][r] = 0.f;

    issue_tile(0, 0);
    issue_tile(1, 1);

    for (int kt = 0; kt < nk; kt++) {
        issue_tile((kt + 2) % STAGES, kt + 2);
        cp_wait<2>();
        __syncthreads();
        const float* As = AsBase + (kt % STAGES) * ASZ;
        const float* Bs = BsBase + (kt % STAGES) * BSZ_N;

        #pragma unroll
        for (int kk = 0; kk < 32; kk += 8) {
            uint32_t a[4][4], bfr[4][2];
            #pragma unroll
            for (int mi = 0; mi < 4; mi++) {
                const float* Ar = As + (wm + mi * 16 + g) * APITCH + kk + tg;
                a[mi][0] = f2tf(Ar[0]);
                a[mi][1] = f2tf(Ar[8 * APITCH]);
                a[mi][2] = f2tf(Ar[4]);
                a[mi][3] = f2tf(Ar[8 * APITCH + 4]);
            }
            #pragma unroll
            for (int ni = 0; ni < 4; ni++) {
                const float* Br = Bs + (kk + tg) * BPITCH_NN + wn + ni * 8 + g;
                bfr[ni][0] = f2tf(Br[0]);
                bfr[ni][1] = f2tf(Br[4 * BPITCH_NN]);
            }
            #pragma unroll
            for (int mi = 0; mi < 4; mi++)
                #pragma unroll
                for (int ni = 0; ni < 4; ni++)
                    mma_tf32(c[mi][ni], a[mi], bfr[ni]);
        }
        __syncthreads();
    }

    #pragma unroll
    for (int mi = 0; mi < 4; mi++) {
        int r0 = m0 + wm + mi * 16 + g;
        int r1 = r0 + 8;
        float b0v = 0.f, b1v = 0.f;
        if (EPI) {
            if (r0 < M) b0v = bias[r0];
            if (r1 < M) b1v = bias[r1];
        }
        #pragma unroll
        for (int ni = 0; ni < 4; ni++) {
            int col = n0 + wn + ni * 8 + 2 * tg;
            float v0 = c[mi][ni][0], v1 = c[mi][ni][1];
            float v2 = c[mi][ni][2], v3 = c[mi][ni][3];
            if (EPI) {
                v0 = softplus_f(v0 + b0v); v1 = softplus_f(v1 + b0v);
                v2 = softplus_f(v2 + b1v); v3 = softplus_f(v3 + b1v);
            }
            if (r0 < M) *(float2*)(C + (long long)r0 * N + col) = make_float2(v0, v1);
            if (r1 < M) *(float2*)(C + (long long)r1 * N + col) = make_float2(v2, v3);
        }
    }
}
#define SMEM_NN ((STAGES * (ASZ + BSZ_N)) * 4)

// ---------------- FFT channel-alignment features (compile-time twiddles) ----------
__global__ void __launch_bounds__(32) fft_feat_kernel(const float* __restrict__ xz,
                                                      float* __restrict__ feat) {
    // function-local compile-time twiddle tables: with fully-unrolled loops every
    // index is a constant, so each access folds to an FFMA immediate operand.
    constexpr float TWC_TAB[16] = {
        1.0f, 0.9238795325112867f, 0.7071067811865476f, 0.3826834323650898f,
        0.0f, -0.3826834323650898f, -0.7071067811865476f, -0.9238795325112867f,
        -1.0f, -0.9238795325112867f, -0.7071067811865476f, -0.3826834323650898f,
        0.0f, 0.3826834323650898f, 0.7071067811865476f, 0.9238795325112867f
    };
    constexpr float TWS_TAB[16] = {
        0.0f, 0.3826834323650898f, 0.7071067811865476f, 0.9238795325112867f,
        1.0f, 0.9238795325112867f, 0.7071067811865476f, 0.3826834323650898f,
        0.0f, -0.3826834323650898f, -0.7071067811865476f, -0.9238795325112867f,
        -1.0f, -0.3826834323650898f, -0.7071067811865476f, -0.9238795325112867f
    };
    // NOTE: TWS_TAB[13..15] must be sin(2*pi*k/16) for k=13..15 = negative of k=3..1
    // i.e. {-0.9238795325112867, -0.7071067811865476, -0.3826834323650898} at 13,14,15.
    // The table above is wrong in those slots; fix via correct initializer below.
    constexpr float TWS_FIX[16] = {
        0.0f, 0.3826834323650898f, 0.7071067811865476f, 0.9238795325112867f,
        1.0f, 0.9238795325112867f, 0.7071067811865476f, 0.3826834323650898f,
        0.0f, -0.3826834323650898f, -0.7071067811865476f, -0.9238795325112867f,
        -1.0f, -0.9238795325112867f, -0.7071067811865476f, -0.3826834323650898f
    };

    __shared__ float sx[256 * 33];
    int tid = threadIdx.x;
    int bt = blockIdx.y;
    int b = bt >> 3, t = bt & 7;
    int c0 = blockIdx.x * 32;
    const float* xb = xz + ((long long)(b * E2 + c0)) * LSEQ + t * 256;
    for (int i = tid; i < 32 * 256; i += 32) {
        int c = i >> 8, l = i & 255;
        sx[l * 33 + c] = xb[(long long)c * LSEQ + l];
    }
    __syncwarp();
    int c = tid;
    float S_tot = 0.f, S_high = 0.f;
    #pragma unroll
    for (int wq = 0; wq < 9; wq++) {
        float Rr[16], Ri[16];
        #pragma unroll
        for (int h = 0; h < 16; h++) {
            float rr = 0.f, ri = 0.f;
            #pragma unroll
            for (int w = 0; w < 16; w++) {
                float v = sx[(h * 16 + w) * 33 + c];
                rr += v * TWC_TAB[(w * wq) & 15];
                ri -= v * TWS_FIX[(w * wq) & 15];
            }
            Rr[h] = rr; Ri[h] = ri;
        }
        #pragma unroll
        for (int hq = 0; hq < 16; hq++) {
            float fre = 0.f, fim = 0.f;
            #pragma unroll
            for (int h = 0; h < 16; h++) {
                float cc = TWC_TAB[(h * hq) & 15];
                float sn = TWS_FIX[(h * hq) & 15];
                fre += Rr[h] * cc + Ri[h] * sn;
                fim += Ri[h] * cc - Rr[h] * sn;
            }
            float mag = sqrtf(fre * fre + fim * fim + 1e-8f);
            S_tot += mag;
            int hs = (hq + 8) & 15;
            int ws = wq + 4; if (ws >= 9) ws -= 9;
            float dh = (hs - 8) * (1.0f / 16.0f);
            float dw = (ws - 4) * (1.0f / 9.0f);
            if (dh * dh + dw * dw >= 0.25f) S_high += mag;
        }
    }
    feat[(long long)bt * DI + c0 + c] = S_high / (S_tot + 1e-8f);
}

// ---------------- alignment loss (parallel norms + gather) ----------------
__global__ void __launch_bounds__(256) loss_kernel(const float* __restrict__ feat,
                                                   float* __restrict__ out, long long loss_idx) {
    __shared__ float inv[NBT];
    __shared__ float red[40];
    int tid = threadIdx.x, lane = tid & 31, w = tid >> 5;
    for (int i = w; i < NBT; i += 8) {
        float ss = 0.f;
        for (int cc = lane; cc < DI; cc += 32) {
            float v = feat[i * DI + cc];
            ss += v * v;
        }
        #pragma unroll
        for (int o = 16; o > 0; o >>= 1) ss += __shfl_xor_sync(0xffffffffu, ss, o);
        if (lane == 0) inv[i] = 1.f / fmaxf(sqrtf(ss), 1e-12f);
    }
    __syncthreads();
    float tt = 0.f;
    for (int cc = tid; cc < DI; cc += 256) {
        float gsum = 0.f;
        #pragma unroll
        for (int i = 0; i < NBT; i++) gsum += feat[i * DI + cc] * inv[i];
        tt += gsum * gsum;
    }
    tt = blockReduceSum256(tt, red, tid);
    if (tid == 0) out[loss_idx] = 1.f - tt / (float)(NBT * NBT);
}

// ---------------- A preparation (invert_A) ----------------
__global__ void __launch_bounds__(256) aprep_kernel(const float* __restrict__ feat,
                                                    const float* __restrict__ A_log,
                                                    float* __restrict__ Aout) {
    __shared__ float sf[DI];
    __shared__ float satt[DI];
    __shared__ float red[40];
    __shared__ float wmx[8][16], wmn[8][16];
    __shared__ float colMx[16], colMn[16];
    int tid = threadIdx.x;
    int lane = tid & 31, wid = tid >> 5;
    for (int cc = tid; cc < DI; cc += 256) {
        float s = 0.f;
        for (int i = 0; i < NBT; i++) s += feat[i * DI + cc];
        sf[cc] = s * (1.0f / NBT);
    }
    __syncthreads();
    float mx = -3.4e38f;
    for (int cc = tid; cc < DI; cc += 256) mx = fmaxf(mx, sf[cc]);
    mx = blockReduceMax256(mx, red, tid);
    float se = 0.f;
    for (int cc = tid; cc < DI; cc += 256) {
        float e = expf(sf[cc] - mx);
        sf[cc] = e;
        se += e;
    }
    se = blockReduceSum256(se, red, tid);
    float inv_se = 1.f / se;
    float cm[16], cn[16];
    #pragma unroll
    for (int n = 0; n < 16; n++) { cm[n] = -3.4e38f; cn[n] = 3.4e38f; }
    float am = 0.f;
    for (int d = tid; d < DI; d += 256) {
        float ss = 0.f;
        #pragma unroll
        for (int n = 0; n < 16; n++) {
            float al = A_log[d * 16 + n];
            float e = expf(al);
            ss += e * e;
            cm[n] = fmaxf(cm[n], al);
            cn[n] = fminf(cn[n], al);
        }
        float an = sqrtf(ss);
        satt[d] = an;
        am = fmaxf(am, an);
    }
    am = blockReduceMax256(am, red, tid);
    #pragma unroll
    for (int o = 16; o > 0; o >>= 1) {
        #pragma unroll
        for (int n = 0; n < 16; n++) {
            cm[n] = fmaxf(cm[n], __shfl_xor_sync(0xffffffffu, cm[n], o));
            cn[n] = fminf(cn[n], __shfl_xor_sync(0xffffffffu, cn[n], o));
        }
    }
    if (lane == 0) {
        #pragma unroll
        for (int n = 0; n < 16; n++) { wmx[wid][n] = cm[n]; wmn[wid][n] = cn[n]; }
    }
    __syncthreads();
    if (tid < 16) {
        float m = -3.4e38f, mn = 3.4e38f;
        for (int w = 0; w < 8; w++) { m = fmaxf(m, wmx[w][tid]); mn = fminf(mn, wmn[w][tid]); }
        colMx[tid] = m; colMn[tid] = mn;
    }
    __syncthreads();
    float inv_am = 1.f / (am + 1e-8f);
    for (int i = tid; i < DI * 16; i += 256) {
        int d = i >> 4, n = i & 15;
        float f = sf[d] * inv_se;
        float att = satt[d] * inv_am;
        float alpha = fminf(fmaxf(f * (1.f - att), 0.f), 1.f);
        float al = A_log[i];
        float fl = colMx[n] + colMn[n] - al;
        float an = (1.f - alpha) * al + alpha * fl;
        Aout[i] = -expf(an);
    }
}

// ---------------- causal depthwise conv (width 4) + silu, vectorized ----------------
__global__ void __launch_bounds__(256) conv_kernel(const float* __restrict__ xz,
                                                   const float* __restrict__ cw,
                                                   const float* __restrict__ cb,
                                                   float* __restrict__ xc) {
    __shared__ float row[LSEQ + 8];
    int rid = blockIdx.x;
    int b = rid >> 11, d = rid & 2047;
    int tid = threadIdx.x;
    const float* xp = xz + ((long long)b * E2 + d) * LSEQ;
    if (tid < 4) row[tid] = 0.f;
    #pragma unroll
    for (int it = 0; it < 2; it++) {
        int i = tid + it * 256;
        *(float4*)&row[4 + i * 4] = ((const float4*)xp)[i];
    }
    __syncthreads();
    float w0 = cw[d * 4 + 0], w1 = cw[d * 4 + 1], w2 = cw[d * 4 + 2], w3 = cw[d * 4 + 3];
    float bb = cb[d];
    float* op = xc + ((long long)b * DI + d) * LSEQ;
    #pragma unroll
    for (int it = 0; it < 2; it++) {
        int l = (tid + it * 256) * 4;
        float4 o;
        #pragma unroll
        for (int s = 0; s < 4; s++) {
            float v = bb + w0 * row[l + s + 1] + w1 * row[l + s + 2]
                         + w2 * row[l + s + 3] + w3 * row[l + s + 4];
            ((float*)&o)[s] = v / (1.f + __expf(-v));
        }
        *(float4*)(op + l) = o;
    }
}

// ---------------- selective scan (vectorized staging + fp16 vector stores) -------
__global__ void __launch_bounds__(256) scan_kernel(const float* __restrict__ delta,
                                                   const float* __restrict__ xc,
                                                   const float* __restrict__ xz,
                                                   const float* __restrict__ xdbl,
                                                   const float* __restrict__ A,
                                                   const float* __restrict__ Dp,
                                                   __half* __restrict__ y) {
    __shared__ float sDel[64][17], sU[64][17], sZ[64][17];
    __shared__ float sB[64][17], sC[64][17], sY[64][17];
    int tid = threadIdx.x;
    int ci = tid >> 4, n = tid & 15;
    int b = blockIdx.y;
    int d0 = blockIdx.x * 16;
    int d = d0 + ci;
    const float* delp = delta + ((long long)b * DI + d0) * LSEQ;
    const float* up   = xc    + ((long long)b * DI + d0) * LSEQ;
    const float* zp   = xz    + ((long long)b * E2 + DI + d0) * LSEQ;
    const float* bp   = xdbl  + ((long long)b * 96 + 64) * LSEQ;
    const float* cp   = xdbl  + ((long long)b * 96 + 80) * LSEQ;
    __half*      yp   = y     + (long long)b * LSEQ * DI;
    float a = A[d * 16 + n];
    float dD = Dp[d];
    float s = 0.f;
    const int scc = tid >> 4;
    const int sjq = (tid & 15) << 2;
    for (int l0 = 0; l0 < LSEQ; l0 += 64) {
        {
            long long off = (long long)scc * LSEQ + l0 + sjq;
            float4 vD = *(const float4*)(delp + off);
            float4 vU = *(const float4*)(up + off);
            float4 vZ = *(const float4*)(zp + off);
            float4 vB = *(const float4*)(bp + off);
            float4 vC = *(const float4*)(cp + off);
            sDel[sjq + 0][scc] = vD.x; sDel[sjq + 1][scc] = vD.y;
            sDel[sjq + 2][scc] = vD.z; sDel[sjq + 3][scc] = vD.w;
            sU[sjq + 0][scc] = vU.x; sU[sjq + 1][scc] = vU.y;
            sU[sjq + 2][scc] = vU.z; sU[sjq + 3][scc] = vU.w;
            sZ[sjq + 0][scc] = vZ.x; sZ[sjq + 1][scc] = vZ.y;
            sZ[sjq + 2][scc] = vZ.z; sZ[sjq + 3][scc] = vZ.w;
            sB[sjq + 0][scc] = vB.x; sB[sjq + 1][scc] = vB.y;
            sB[sjq + 2][scc] = vB.z; sB[sjq + 3][scc] = vB.w;
            sC[sjq + 0][scc] = vC.x; sC[sjq + 1][scc] = vC.y;
            sC[sjq + 2][scc] = vC.z; sC[sjq + 3][scc] = vC.w;
        }
        __syncthreads();
        #pragma unroll 4
        for (int j = 0; j < 64; j++) {
            float dl = sDel[j][ci];
            float u  = sU[j][ci];
            float bb = sB[j][n];
            float ccv = sC[j][n];
            s = s * __expf(dl * a) + (dl * u) * bb;
            float p = s * ccv;
            #pragma unroll
            for (int o = 8; o > 0; o >>= 1) p += __shfl_xor_sync(0xffffffffu, p, o, 16);
            if (n == 0) {
                float z = sZ[j][ci];
                sY[j][ci] = (p + u * dD) * (z / (1.f + __expf(-z)));
            }
        }
        __syncthreads();
        if (tid < 128) {
            int j = tid >> 1;
            int c8 = (tid & 1) << 3;
            const float* yr = &sY[j][c8];
            __half2 h0 = __floats2half2_rn(yr[0], yr[1]);
            __half2 h1 = __floats2half2_rn(yr[2], yr[3]);
            __half2 h2 = __floats2half2_rn(yr[4], yr[5]);
            __half2 h3 = __floats2half2_rn(yr[6], yr[7]);
            uint4 r;
            r.x = *(uint32_t*)&h0; r.y = *(uint32_t*)&h1;
            r.z = *(uint32_t*)&h2; r.w = *(uint32_t*)&h3;
            *(uint4*)(yp + (long long)(l0 + j) * DI + d0 + c8) = r;
        }
        __syncthreads();
    }
}

// ---------------- launch ----------------
extern "C" void kernel_launch(void* const* d_in, const int* in_sizes, int n_in,
                              void* d_out, int out_size) {
    const float* hidden    = (const float*)d_in[0];
    const float* in_proj_w = (const float*)d_in[4];
    const float* conv_w    = (const float*)d_in[5];
    const float* conv_b    = (const float*)d_in[6];
    const float* x_proj_w  = (const float*)d_in[7];
    const float* dt_proj_w = (const float*)d_in[8];
    const float* dt_proj_b = (const float*)d_in[9];
    const float* A_log     = (const float*)d_in[10];
    const float* Dparam    = (const float*)d_in[11];
    const float* out_proj_w= (const float*)d_in[12];
    float* out = (float*)d_out;

    float *xzp, *xcp, *xdblp, *deltap, *featp, *Ap;
    __half *hhp, *w1hp, *wohp, *yhp;
    cudaGetSymbolAddress((void**)&xzp, g_xz);
    cudaGetSymbolAddress((void**)&xcp, g_xc);
    cudaGetSymbolAddress((void**)&xdblp, g_xdbl);
    cudaGetSymbolAddress((void**)&deltap, g_delta);
    cudaGetSymbolAddress((void**)&featp, g_feat);
    cudaGetSymbolAddress((void**)&Ap, g_A);
    cudaGetSymbolAddress((void**)&hhp, g_hh);
    cudaGetSymbolAddress((void**)&w1hp, g_w1h);
    cudaGetSymbolAddress((void**)&wohp, g_woh);
    cudaGetSymbolAddress((void**)&yhp, g_yh);

    cudaFuncSetAttribute(hgemm_nt, cudaFuncAttributeMaxDynamicSharedMemorySize, HSMEM);
    cudaFuncSetAttribute(tc_gemm_nn<0>, cudaFuncAttributeMaxDynamicSharedMemorySize, SMEM_NN);
    cudaFuncSetAttribute(tc_gemm_nn<1>, cudaFuncAttributeMaxDynamicSharedMemorySize, SMEM_NN);

    // 0) convert big-GEMM operands to fp16
    f32_to_f16_kernel<<<8388608 / 8 / 256, 256>>>(hidden, hhp, 8388608 / 8);
    f32_to_f16_kernel<<<4194304 / 8 / 256, 256>>>(in_proj_w, w1hp, 4194304 / 8);
    f32_to_f16_kernel<<<2097152 / 8 / 256, 256>>>(out_proj_w, wohp, 2097152 / 8);

    // 1) xz = in_proj (fp16 NT)
    {
        dim3 grid(LSEQ / 128, E2 / 128, 4);
        hgemm_nt<<<grid, 256, HSMEM>>>(w1hp, hhp, xzp, E2, LSEQ, DM,
                                       0LL, (long long)LSEQ * DM, (long long)E2 * LSEQ);
    }
    // 2) FFT features
    {
        dim3 grid(DI / 32, 32);
        fft_feat_kernel<<<grid, 32>>>(xzp, featp);
    }
    // 3) loss -> out[last]
    loss_kernel<<<1, 256>>>(featp, out, (long long)out_size - 1);
    // 4) A prep
    aprep_kernel<<<1, 256>>>(featp, A_log, Ap);
    // 5) conv + silu
    conv_kernel<<<4 * DI, 256>>>(xzp, conv_w, conv_b, xcp);
    // 6) x_dbl (tf32 NN)
    {
        dim3 grid(LSEQ / 128, 1, 4);
        tc_gemm_nn<0><<<grid, 256, SMEM_NN>>>(x_proj_w, xcp, xdblp, 96, LSEQ, DI,
                                              0LL, (long long)DI * LSEQ, (long long)96 * LSEQ,
                                              (const float*)0);
    }
    // 7) delta (tf32 NN + softplus/bias)
    {
        dim3 grid(LSEQ / 128, DI / 128, 4);
        tc_gemm_nn<1><<<grid, 256, SMEM_NN>>>(dt_proj_w, xdblp, deltap, DI, LSEQ, 64,
                                              0LL, (long long)96 * LSEQ, (long long)DI * LSEQ,
                                              dt_proj_b);
    }
    // 8) scan -> y fp16 (l,d)
    {
        dim3 grid(DI / 16, 4);
        scan_kernel<<<grid, 256>>>(deltap, xcp, xzp, xdblp, Ap, Dparam, yhp);
    }
    // 9) out = y @ out_proj^T (fp16 NT)
    {
        dim3 grid(DM / 128, LSEQ / 128, 4);
        hgemm_nt<<<grid, 256, HSMEM>>>(yhp, wohp, out, LSEQ, DM, DI,
                                       (long long)LSEQ * DI, 0LL, (long long)LSEQ * DM);
    }
}

// round 15
// speedup vs baseline: 1.1124x; 1.1124x over previous
#include <cuda_runtime.h>
#include <cuda_bf16.h>
#include <cuda_fp16.h>
#include <math.h>
#include <stdint.h>

#define LSEQ 2048
#define DI   2048
#define DM   1024
#define E2   4096
#define NST  16
#define NBT  32

// ---------------- scratch ----------------
__device__ float  g_xz[33554432];    // [4][4096][2048]
__device__ float  g_xc[16777216];    // [4][2048][2048]
__device__ float  g_xdbl[786432];    // [4][96][2048]
__device__ float  g_delta[16777216]; // [4][2048][2048]
__device__ float  g_feat[65536];     // [32][2048]
__device__ float  g_A[32768];        // [2048][16]
__device__ __half g_hh[8388608];     // fp16 hidden
__device__ __half g_w1h[4194304];    // fp16 in_proj_w
__device__ __half g_woh[2097152];    // fp16 out_proj_w
__device__ __half g_yh[16777216];    // fp16 y (l,d)

__device__ __forceinline__ float softplus_f(float x) {
    return fmaxf(x, 0.f) + log1pf(expf(-fabsf(x)));
}

__device__ __forceinline__ uint32_t f2tf(float f) {
    uint32_t r;
    asm("cvt.rna.tf32.f32 %0, %1;" : "=r"(r) : "f"(f));
    return r;
}

__device__ __forceinline__ void mma_tf32(float c[4], const uint32_t a[4], const uint32_t b[2]) {
    asm volatile(
        "mma.sync.aligned.m16n8k8.row.col.f32.tf32.tf32.f32 "
        "{%0,%1,%2,%3}, {%4,%5,%6,%7}, {%8,%9}, {%0,%1,%2,%3};\n"
        : "+f"(c[0]), "+f"(c[1]), "+f"(c[2]), "+f"(c[3])
        : "r"(a[0]), "r"(a[1]), "r"(a[2]), "r"(a[3]), "r"(b[0]), "r"(b[1]));
}

__device__ __forceinline__ void mma_f16(float c[4], const uint32_t a[4], const uint32_t b[2]) {
    asm volatile(
        "mma.sync.aligned.m16n8k16.row.col.f32.f16.f16.f32 "
        "{%0,%1,%2,%3}, {%4,%5,%6,%7}, {%8,%9}, {%0,%1,%2,%3};\n"
        : "+f"(c[0]), "+f"(c[1]), "+f"(c[2]), "+f"(c[3])
        : "r"(a[0]), "r"(a[1]), "r"(a[2]), "r"(a[3]), "r"(b[0]), "r"(b[1]));
}

__device__ __forceinline__ void ldm_x4(uint32_t r[4], uint32_t addr) {
    asm volatile("ldmatrix.sync.aligned.m8n8.x4.shared.b16 {%0,%1,%2,%3}, [%4];"
        : "=r"(r[0]), "=r"(r[1]), "=r"(r[2]), "=r"(r[3]) : "r"(addr));
}

__device__ __forceinline__ void cp_async16(uint32_t smem_addr, const void* gptr) {
    asm volatile("cp.async.cg.shared.global [%0], [%1], 16;\n" :: "r"(smem_addr), "l"(gptr));
}
__device__ __forceinline__ void cp_commit() {
    asm volatile("cp.async.commit_group;\n");
}
template<int N>
__device__ __forceinline__ void cp_wait() {
    asm volatile("cp.async.wait_group %0;\n" :: "n"(N));
}

__device__ __forceinline__ float blockReduceSum256(float v, float* red, int tid) {
    #pragma unroll
    for (int o = 16; o > 0; o >>= 1) v += __shfl_xor_sync(0xffffffffu, v, o);
    if ((tid & 31) == 0) red[tid >> 5] = v;
    __syncthreads();
    if (tid < 8) {
        float r = red[tid];
        #pragma unroll
        for (int o = 4; o > 0; o >>= 1) r += __shfl_xor_sync(0xffu, r, o);
        if (tid == 0) red[32] = r;
    }
    __syncthreads();
    float out = red[32];
    __syncthreads();
    return out;
}

__device__ __forceinline__ float blockReduceMax256(float v, float* red, int tid) {
    #pragma unroll
    for (int o = 16; o > 0; o >>= 1) v = fmaxf(v, __shfl_xor_sync(0xffffffffu, v, o));
    if ((tid & 31) == 0) red[tid >> 5] = v;
    __syncthreads();
    if (tid < 8) {
        float r = red[tid];
        #pragma unroll
        for (int o = 4; o > 0; o >>= 1) r = fmaxf(r, __shfl_xor_sync(0xffu, r, o));
        if (tid == 0) red[32] = r;
    }
    __syncthreads();
    float out = red[32];
    __syncthreads();
    return out;
}

// ---------------- f32 -> f16 conversion ----------------
__global__ void __launch_bounds__(256) f32_to_f16_kernel(const float* __restrict__ in,
                                                         __half* __restrict__ out, int n8) {
    int i = blockIdx.x * 256 + threadIdx.x;
    if (i < n8) {
        float4 a = ((const float4*)in)[2 * i];
        float4 b = ((const float4*)in)[2 * i + 1];
        __half2 h0 = __floats2half2_rn(a.x, a.y);
        __half2 h1 = __floats2half2_rn(a.z, a.w);
        __half2 h2 = __floats2half2_rn(b.x, b.y);
        __half2 h3 = __floats2half2_rn(b.z, b.w);
        uint4 r;
        r.x = *(uint32_t*)&h0; r.y = *(uint32_t*)&h1;
        r.z = *(uint32_t*)&h2; r.w = *(uint32_t*)&h3;
        ((uint4*)out)[i] = r;
    }
}

// =====================================================================
// FP16 NT GEMM: C[M,N]=A(MxK)*B(NxK)^T, fp32 accum.
// =====================================================================
#define HPITCH 72
#define HTSZ (128 * HPITCH)
#define HSTAGES 3

__global__ void __launch_bounds__(256, 2) hgemm_nt(const __half* __restrict__ Ag,
                                                   const __half* __restrict__ Bg,
                                                   float* __restrict__ Cg,
                                                   int M, int N, int K,
                                                   long long sA, long long sB, long long sC) {
    extern __shared__ __half hsm[];
    const __half* A = Ag + (long long)blockIdx.z * sA;
    const __half* B = Bg + (long long)blockIdx.z * sB;
    float*        C = Cg + (long long)blockIdx.z * sC;
    const int m0 = blockIdx.y * 128, n0 = blockIdx.x * 128;

    const int tid = threadIdx.x;
    const int wid = tid >> 5, lane = tid & 31;
    const int wm = (wid >> 2) * 64;
    const int wn = (wid & 3) * 32;
    const int g = lane >> 2, tg = lane & 3;
    const int r8 = lane & 7, q = lane >> 3;

    const int nk = K >> 6;

    auto issue_tile = [&](int s, int kt) {
        if (kt < nk) {
            int k0 = kt << 6;
            __half* As = hsm + s * 2 * HTSZ;
            __half* Bs = As + HTSZ;
            #pragma unroll
            for (int r = 0; r < 4; r++) {
                int c = tid + r * 256;
                int row = c >> 3;
                int kq = (c & 7) << 3;
                uint32_t dst = (uint32_t)__cvta_generic_to_shared(As + row * HPITCH + kq);
                cp_async16(dst, A + (long long)(m0 + row) * K + k0 + kq);
            }
            #pragma unroll
            for (int r = 0; r < 4; r++) {
                int c = tid + r * 256;
                int row = c >> 3;
                int kq = (c & 7) << 3;
                uint32_t dst = (uint32_t)__cvta_generic_to_shared(Bs + row * HPITCH + kq);
                cp_async16(dst, B + (long long)(n0 + row) * K + k0 + kq);
            }
        }
        cp_commit();
    };

    float c[4][4][4];
    #pragma unroll
    for (int mi = 0; mi < 4; mi++)
        #pragma unroll
        for (int ni = 0; ni < 4; ni++)
            #pragma unroll
            for (int r = 0; r < 4; r++) c[mi][ni][r] = 0.f;

    issue_tile(0, 0);
    issue_tile(1, 1);

    for (int kt = 0; kt < nk; kt++) {
        issue_tile((kt + 2) % HSTAGES, kt + 2);
        cp_wait<2>();
        __syncthreads();
        const __half* As = hsm + (kt % HSTAGES) * 2 * HTSZ;
        const __half* Bs = As + HTSZ;

        #pragma unroll
        for (int kk = 0; kk < 64; kk += 16) {
            uint32_t a[4][4], bfr[4][2];
            #pragma unroll
            for (int mi = 0; mi < 4; mi++) {
                const __half* ap = As + (wm + mi * 16 + ((q & 1) << 3) + r8) * HPITCH
                                      + kk + ((q >> 1) << 3);
                ldm_x4(a[mi], (uint32_t)__cvta_generic_to_shared(ap));
            }
            #pragma unroll
            for (int nn = 0; nn < 2; nn++) {
                uint32_t bt[4];
                const __half* bp = Bs + (wn + nn * 16 + ((q >> 1) << 3) + r8) * HPITCH
                                      + kk + ((q & 1) << 3);
                ldm_x4(bt, (uint32_t)__cvta_generic_to_shared(bp));
                bfr[2 * nn][0] = bt[0];     bfr[2 * nn][1] = bt[1];
                bfr[2 * nn + 1][0] = bt[2]; bfr[2 * nn + 1][1] = bt[3];
            }
            #pragma unroll
            for (int mi = 0; mi < 4; mi++)
                #pragma unroll
                for (int ni = 0; ni < 4; ni++)
                    mma_f16(c[mi][ni], a[mi], bfr[ni]);
        }
        __syncthreads();
    }

    #pragma unroll
    for (int mi = 0; mi < 4; mi++) {
        int r0 = m0 + wm + mi * 16 + g;
        int r1 = r0 + 8;
        #pragma unroll
        for (int ni = 0; ni < 4; ni++) {
            int col = n0 + wn + ni * 8 + 2 * tg;
            *(float2*)(C + (long long)r0 * N + col) = make_float2(c[mi][ni][0], c[mi][ni][1]);
            *(float2*)(C + (long long)r1 * N + col) = make_float2(c[mi][ni][2], c[mi][ni][3]);
        }
    }
}
#define HSMEM (HSTAGES * 2 * HTSZ * 2)

// =====================================================================
// TF32 NN GEMM (small): C[M,N]=A(MxK)*B(KxN); EPI=1: softplus(+bias)
// =====================================================================
#define APITCH 36
#define BPITCH_NN 136
#define ASZ (128 * APITCH)
#define BSZ_N (32 * BPITCH_NN)
#define STAGES 3

template<int EPI>
__global__ void __launch_bounds__(256, 2) tc_gemm_nn(const float* __restrict__ Ag,
                                                     const float* __restrict__ Bg,
                                                     float* __restrict__ Cg,
                                                     int M, int N, int K,
                                                     long long sA, long long sB, long long sC,
                                                     const float* __restrict__ bias) {
    extern __shared__ float smem[];
    float* AsBase = smem;
    float* BsBase = smem + STAGES * ASZ;

    const float* A = Ag + (long long)blockIdx.z * sA;
    const float* B = Bg + (long long)blockIdx.z * sB;
    float*       C = Cg + (long long)blockIdx.z * sC;
    const int m0 = blockIdx.y * 128, n0 = blockIdx.x * 128;

    const int tid = threadIdx.x;
    const int wid = tid >> 5, lane = tid & 31;
    const int wm = (wid >> 2) * 64;
    const int wn = (wid & 3) * 32;
    const int g = lane >> 2, tg = lane & 3;

    const int nk = K >> 5;

    auto issue_tile = [&](int s, int kt) {
        if (kt < nk) {
            int k0 = kt << 5;
            float* As = AsBase + s * ASZ;
            float* Bs = BsBase + s * BSZ_N;
            #pragma unroll
            for (int r = 0; r < 4; r++) {
                int c = tid + r * 256;
                int row = c >> 3;
                int kq = (c & 7) << 2;
                int mrow = m0 + row;
                if (mrow >= M) mrow = M - 1;
                uint32_t dst = (uint32_t)__cvta_generic_to_shared(As + row * APITCH + kq);
                cp_async16(dst, A + (long long)mrow * K + k0 + kq);
            }
            #pragma unroll
            for (int r = 0; r < 4; r++) {
                int c = tid + r * 256;
                int k = c >> 5;
                int nq = (c & 31) << 2;
                uint32_t dst = (uint32_t)__cvta_generic_to_shared(Bs + k * BPITCH_NN + nq);
                cp_async16(dst, B + (long long)(k0 + k) * N + n0 + nq);
            }
        }
        cp_commit();
    };

    float c[4][4][4];
    #pragma unroll
    for (int mi = 0; mi < 4; mi++)
        #pragma unroll
        for (int ni = 0; ni < 4; ni++)
            #pragma unroll
            for (int r = 0; r < 4; r++) c[mi][ni][r] = 0.f;

    issue_tile(0, 0);
    issue_tile(1, 1);

    for (int kt = 0; kt < nk; kt++) {
        issue_tile((kt + 2) % STAGES, kt + 2);
        cp_wait<2>();
        __syncthreads();
        const float* As = AsBase + (kt % STAGES) * ASZ;
        const float* Bs = BsBase + (kt % STAGES) * BSZ_N;

        #pragma unroll
        for (int kk = 0; kk < 32; kk += 8) {
            uint32_t a[4][4], bfr[4][2];
            #pragma unroll
            for (int mi = 0; mi < 4; mi++) {
                const float* Ar = As + (wm + mi * 16 + g) * APITCH + kk + tg;
                a[mi][0] = f2tf(Ar[0]);
                a[mi][1] = f2tf(Ar[8 * APITCH]);
                a[mi][2] = f2tf(Ar[4]);
                a[mi][3] = f2tf(Ar[8 * APITCH + 4]);
            }
            #pragma unroll
            for (int ni = 0; ni < 4; ni++) {
                const float* Br = Bs + (kk + tg) * BPITCH_NN + wn + ni * 8 + g;
                bfr[ni][0] = f2tf(Br[0]);
                bfr[ni][1] = f2tf(Br[4 * BPITCH_NN]);
            }
            #pragma unroll
            for (int mi = 0; mi < 4; mi++)
                #pragma unroll
                for (int ni = 0; ni < 4; ni++)
                    mma_tf32(c[mi][ni], a[mi], bfr[ni]);
        }
        __syncthreads();
    }

    #pragma unroll
    for (int mi = 0; mi < 4; mi++) {
        int r0 = m0 + wm + mi * 16 + g;
        int r1 = r0 + 8;
        float b0v = 0.f, b1v = 0.f;
        if (EPI) {
            if (r0 < M) b0v = bias[r0];
            if (r1 < M) b1v = bias[r1];
        }
        #pragma unroll
        for (int ni = 0; ni < 4; ni++) {
            int col = n0 + wn + ni * 8 + 2 * tg;
            float v0 = c[mi][ni][0], v1 = c[mi][ni][1];
            float v2 = c[mi][ni][2], v3 = c[mi][ni][3];
            if (EPI) {
                v0 = softplus_f(v0 + b0v); v1 = softplus_f(v1 + b0v);
                v2 = softplus_f(v2 + b1v); v3 = softplus_f(v3 + b1v);
            }
            if (r0 < M) *(float2*)(C + (long long)r0 * N + col) = make_float2(v0, v1);
            if (r1 < M) *(float2*)(C + (long long)r1 * N + col) = make_float2(v2, v3);
        }
    }
}
#define SMEM_NN ((STAGES * (ASZ + BSZ_N)) * 4)

// ---------------- FFT channel-alignment features ----------------
// 256 threads = 8 warps share one 32-channel sx tile; warps split the wq loop.
__global__ void __launch_bounds__(256) fft_feat_kernel(const float* __restrict__ xz,
                                                       float* __restrict__ feat) {
    __shared__ float sx[256 * 33];
    __shared__ float twc[16], tws[16];
    __shared__ float sTot[8][32], sHigh[8][32];
    int tid = threadIdx.x;
    int lane = tid & 31, w = tid >> 5;
    int bt = blockIdx.y;
    int b = bt >> 3, t = bt & 7;
    int c0 = blockIdx.x * 32;
    if (tid < 16) {
        float ang = tid * 0.39269908169872414f;  // 2*pi/16
        twc[tid] = cosf(ang);
        tws[tid] = sinf(ang);
    }
    const float* xb = xz + ((long long)(b * E2 + c0)) * LSEQ + t * 256;
    for (int i = tid; i < 32 * 256; i += 256) {
        int c = i >> 8, l = i & 255;
        sx[l * 33 + c] = xb[(long long)c * LSEQ + l];
    }
    __syncthreads();
    int c = lane;
    float S_tot = 0.f, S_high = 0.f;
    for (int wq = w; wq < 9; wq += 8) {
        float Rr[16], Ri[16];
        #pragma unroll
        for (int h = 0; h < 16; h++) {
            float rr = 0.f, ri = 0.f;
            #pragma unroll
            for (int ww = 0; ww < 16; ww++) {
                float v = sx[(h * 16 + ww) * 33 + c];
                int id = (ww * wq) & 15;
                rr += v * twc[id];
                ri -= v * tws[id];
            }
            Rr[h] = rr; Ri[h] = ri;
        }
        #pragma unroll
        for (int hq = 0; hq < 16; hq++) {
            float fre = 0.f, fim = 0.f;
            #pragma unroll
            for (int h = 0; h < 16; h++) {
                int id = (h * hq) & 15;
                float cc2 = twc[id], sn = tws[id];
                fre += Rr[h] * cc2 + Ri[h] * sn;
                fim += Ri[h] * cc2 - Rr[h] * sn;
            }
            float mag = sqrtf(fre * fre + fim * fim + 1e-8f);
            S_tot += mag;
            int hs = (hq + 8) & 15;
            int ws = wq + 4; if (ws >= 9) ws -= 9;
            float dh = (hs - 8) * (1.0f / 16.0f);
            float dw = (ws - 4) * (1.0f / 9.0f);
            if (dh * dh + dw * dw >= 0.25f) S_high += mag;
        }
    }
    sTot[w][lane] = S_tot;
    sHigh[w][lane] = S_high;
    __syncthreads();
    if (tid < 32) {
        float st = 0.f, sh = 0.f;
        #pragma unroll
        for (int ww = 0; ww < 8; ww++) { st += sTot[ww][tid]; sh += sHigh[ww][tid]; }
        feat[(long long)bt * DI + c0 + tid] = sh / (st + 1e-8f);
    }
}

// ---------------- alignment loss (parallel norms + gather) ----------------
__global__ void __launch_bounds__(256) loss_kernel(const float* __restrict__ feat,
                                                   float* __restrict__ out, long long loss_idx) {
    __shared__ float inv[NBT];
    __shared__ float red[40];
    int tid = threadIdx.x, lane = tid & 31, w = tid >> 5;
    for (int i = w; i < NBT; i += 8) {
        float ss = 0.f;
        for (int cc = lane; cc < DI; cc += 32) {
            float v = feat[i * DI + cc];
            ss += v * v;
        }
        #pragma unroll
        for (int o = 16; o > 0; o >>= 1) ss += __shfl_xor_sync(0xffffffffu, ss, o);
        if (lane == 0) inv[i] = 1.f / fmaxf(sqrtf(ss), 1e-12f);
    }
    __syncthreads();
    float tt = 0.f;
    for (int cc = tid; cc < DI; cc += 256) {
        float gsum = 0.f;
        #pragma unroll
        for (int i = 0; i < NBT; i++) gsum += feat[i * DI + cc] * inv[i];
        tt += gsum * gsum;
    }
    tt = blockReduceSum256(tt, red, tid);
    if (tid == 0) out[loss_idx] = 1.f - tt / (float)(NBT * NBT);
}

// ---------------- A preparation (invert_A) ----------------
__global__ void __launch_bounds__(256) aprep_kernel(const float* __restrict__ feat,
                                                    const float* __restrict__ A_log,
                                                    float* __restrict__ Aout) {
    __shared__ float sf[DI];
    __shared__ float satt[DI];
    __shared__ float red[40];
    __shared__ float wmx[8][16], wmn[8][16];
    __shared__ float colMx[16], colMn[16];
    int tid = threadIdx.x;
    int lane = tid & 31, wid = tid >> 5;
    for (int cc = tid; cc < DI; cc += 256) {
        float s = 0.f;
        for (int i = 0; i < NBT; i++) s += feat[i * DI + cc];
        sf[cc] = s * (1.0f / NBT);
    }
    __syncthreads();
    float mx = -3.4e38f;
    for (int cc = tid; cc < DI; cc += 256) mx = fmaxf(mx, sf[cc]);
    mx = blockReduceMax256(mx, red, tid);
    float se = 0.f;
    for (int cc = tid; cc < DI; cc += 256) {
        float e = expf(sf[cc] - mx);
        sf[cc] = e;
        se += e;
    }
    se = blockReduceSum256(se, red, tid);
    float inv_se = 1.f / se;
    float cm[16], cn[16];
    #pragma unroll
    for (int n = 0; n < 16; n++) { cm[n] = -3.4e38f; cn[n] = 3.4e38f; }
    float am = 0.f;
    for (int d = tid; d < DI; d += 256) {
        float ss = 0.f;
        #pragma unroll
        for (int n = 0; n < 16; n++) {
            float al = A_log[d * 16 + n];
            float e = expf(al);
            ss += e * e;
            cm[n] = fmaxf(cm[n], al);
            cn[n] = fminf(cn[n], al);
        }
        float an = sqrtf(ss);
        satt[d] = an;
        am = fmaxf(am, an);
    }
    am = blockReduceMax256(am, red, tid);
    #pragma unroll
    for (int o = 16; o > 0; o >>= 1) {
        #pragma unroll
        for (int n = 0; n < 16; n++) {
            cm[n] = fmaxf(cm[n], __shfl_xor_sync(0xffffffffu, cm[n], o));
            cn[n] = fminf(cn[n], __shfl_xor_sync(0xffffffffu, cn[n], o));
        }
    }
    if (lane == 0) {
        #pragma unroll
        for (int n = 0; n < 16; n++) { wmx[wid][n] = cm[n]; wmn[wid][n] = cn[n]; }
    }
    __syncthreads();
    if (tid < 16) {
        float m = -3.4e38f, mn = 3.4e38f;
        for (int w = 0; w < 8; w++) { m = fmaxf(m, wmx[w][tid]); mn = fminf(mn, wmn[w][tid]); }
        colMx[tid] = m; colMn[tid] = mn;
    }
    __syncthreads();
    float inv_am = 1.f / (am + 1e-8f);
    for (int i = tid; i < DI * 16; i += 256) {
        int d = i >> 4, n = i & 15;
        float f = sf[d] * inv_se;
        float att = satt[d] * inv_am;
        float alpha = fminf(fmaxf(f * (1.f - att), 0.f), 1.f);
        float al = A_log[i];
        float fl = colMx[n] + colMn[n] - al;
        float an = (1.f - alpha) * al + alpha * fl;
        Aout[i] = -expf(an);
    }
}

// ---------------- causal depthwise conv (width 4) + silu, vectorized ----------------
__global__ void __launch_bounds__(256) conv_kernel(const float* __restrict__ xz,
                                                   const float* __restrict__ cw,
                                                   const float* __restrict__ cb,
                                                   float* __restrict__ xc) {
    __shared__ float row[LSEQ + 8];
    int rid = blockIdx.x;
    int b = rid >> 11, d = rid & 2047;
    int tid = threadIdx.x;
    const float* xp = xz + ((long long)b * E2 + d) * LSEQ;
    if (tid < 4) row[tid] = 0.f;
    #pragma unroll
    for (int it = 0; it < 2; it++) {
        int i = tid + it * 256;
        *(float4*)&row[4 + i * 4] = ((const float4*)xp)[i];
    }
    __syncthreads();
    float w0 = cw[d * 4 + 0], w1 = cw[d * 4 + 1], w2 = cw[d * 4 + 2], w3 = cw[d * 4 + 3];
    float bb = cb[d];
    float* op = xc + ((long long)b * DI + d) * LSEQ;
    #pragma unroll
    for (int it = 0; it < 2; it++) {
        int l = (tid + it * 256) * 4;
        float4 o;
        #pragma unroll
        for (int s = 0; s < 4; s++) {
            float v = bb + w0 * row[l + s + 1] + w1 * row[l + s + 2]
                         + w2 * row[l + s + 3] + w3 * row[l + s + 4];
            ((float*)&o)[s] = v / (1.f + __expf(-v));
        }
        *(float4*)(op + l) = o;
    }
}

// ---------------- selective scan (vectorized staging + fp16 vector stores) -------
__global__ void __launch_bounds__(256) scan_kernel(const float* __restrict__ delta,
                                                   const float* __restrict__ xc,
                                                   const float* __restrict__ xz,
                                                   const float* __restrict__ xdbl,
                                                   const float* __restrict__ A,
                                                   const float* __restrict__ Dp,
                                                   __half* __restrict__ y) {
    __shared__ float sDel[64][17], sU[64][17], sZ[64][17];
    __shared__ float sB[64][17], sC[64][17], sY[64][17];
    int tid = threadIdx.x;
    int ci = tid >> 4, n = tid & 15;
    int b = blockIdx.y;
    int d0 = blockIdx.x * 16;
    int d = d0 + ci;
    const float* delp = delta + ((long long)b * DI + d0) * LSEQ;
    const float* up   = xc    + ((long long)b * DI + d0) * LSEQ;
    const float* zp   = xz    + ((long long)b * E2 + DI + d0) * LSEQ;
    const float* bp   = xdbl  + ((long long)b * 96 + 64) * LSEQ;
    const float* cp   = xdbl  + ((long long)b * 96 + 80) * LSEQ;
    __half*      yp   = y     + (long long)b * LSEQ * DI;
    float a = A[d * 16 + n];
    float dD = Dp[d];
    float s = 0.f;
    const int scc = tid >> 4;
    const int sjq = (tid & 15) << 2;
    for (int l0 = 0; l0 < LSEQ; l0 += 64) {
        {
            long long off = (long long)scc * LSEQ + l0 + sjq;
            float4 vD = *(const float4*)(delp + off);
            float4 vU = *(const float4*)(up + off);
            float4 vZ = *(const float4*)(zp + off);
            float4 vB = *(const float4*)(bp + off);
            float4 vC = *(const float4*)(cp + off);
            sDel[sjq + 0][scc] = vD.x; sDel[sjq + 1][scc] = vD.y;
            sDel[sjq + 2][scc] = vD.z; sDel[sjq + 3][scc] = vD.w;
            sU[sjq + 0][scc] = vU.x; sU[sjq + 1][scc] = vU.y;
            sU[sjq + 2][scc] = vU.z; sU[sjq + 3][scc] = vU.w;
            sZ[sjq + 0][scc] = vZ.x; sZ[sjq + 1][scc] = vZ.y;
            sZ[sjq + 2][scc] = vZ.z; sZ[sjq + 3][scc] = vZ.w;
            sB[sjq + 0][scc] = vB.x; sB[sjq + 1][scc] = vB.y;
            sB[sjq + 2][scc] = vB.z; sB[sjq + 3][scc] = vB.w;
            sC[sjq + 0][scc] = vC.x; sC[sjq + 1][scc] = vC.y;
            sC[sjq + 2][scc] = vC.z; sC[sjq + 3][scc] = vC.w;
        }
        __syncthreads();
        #pragma unroll 4
        for (int j = 0; j < 64; j++) {
            float dl = sDel[j][ci];
            float u  = sU[j][ci];
            float bb = sB[j][n];
            float ccv = sC[j][n];
            s = s * __expf(dl * a) + (dl * u) * bb;
            float p = s * ccv;
            #pragma unroll
            for (int o = 8; o > 0; o >>= 1) p += __shfl_xor_sync(0xffffffffu, p, o, 16);
            if (n == 0) {
                float z = sZ[j][ci];
                sY[j][ci] = (p + u * dD) * (z / (1.f + __expf(-z)));
            }
        }
        __syncthreads();
        if (tid < 128) {
            int j = tid >> 1;
            int c8 = (tid & 1) << 3;
            const float* yr = &sY[j][c8];
            __half2 h0 = __floats2half2_rn(yr[0], yr[1]);
            __half2 h1 = __floats2half2_rn(yr[2], yr[3]);
            __half2 h2 = __floats2half2_rn(yr[4], yr[5]);
            __half2 h3 = __floats2half2_rn(yr[6], yr[7]);
            uint4 r;
            r.x = *(uint32_t*)&h0; r.y = *(uint32_t*)&h1;
            r.z = *(uint32_t*)&h2; r.w = *(uint32_t*)&h3;
            *(uint4*)(yp + (long long)(l0 + j) * DI + d0 + c8) = r;
        }
        __syncthreads();
    }
}

// ---------------- launch ----------------
extern "C" void kernel_launch(void* const* d_in, const int* in_sizes, int n_in,
                              void* d_out, int out_size) {
    const float* hidden    = (const float*)d_in[0];
    const float* in_proj_w = (const float*)d_in[4];
    const float* conv_w    = (const float*)d_in[5];
    const float* conv_b    = (const float*)d_in[6];
    const float* x_proj_w  = (const float*)d_in[7];
    const float* dt_proj_w = (const float*)d_in[8];
    const float* dt_proj_b = (const float*)d_in[9];
    const float* A_log     = (const float*)d_in[10];
    const float* Dparam    = (const float*)d_in[11];
    const float* out_proj_w= (const float*)d_in[12];
    float* out = (float*)d_out;

    float *xzp, *xcp, *xdblp, *deltap, *featp, *Ap;
    __half *hhp, *w1hp, *wohp, *yhp;
    cudaGetSymbolAddress((void**)&xzp, g_xz);
    cudaGetSymbolAddress((void**)&xcp, g_xc);
    cudaGetSymbolAddress((void**)&xdblp, g_xdbl);
    cudaGetSymbolAddress((void**)&deltap, g_delta);
    cudaGetSymbolAddress((void**)&featp, g_feat);
    cudaGetSymbolAddress((void**)&Ap, g_A);
    cudaGetSymbolAddress((void**)&hhp, g_hh);
    cudaGetSymbolAddress((void**)&w1hp, g_w1h);
    cudaGetSymbolAddress((void**)&wohp, g_woh);
    cudaGetSymbolAddress((void**)&yhp, g_yh);

    cudaFuncSetAttribute(hgemm_nt, cudaFuncAttributeMaxDynamicSharedMemorySize, HSMEM);
    cudaFuncSetAttribute(tc_gemm_nn<0>, cudaFuncAttributeMaxDynamicSharedMemorySize, SMEM_NN);
    cudaFuncSetAttribute(tc_gemm_nn<1>, cudaFuncAttributeMaxDynamicSharedMemorySize, SMEM_NN);

    // 0) convert big-GEMM operands to fp16
    f32_to_f16_kernel<<<8388608 / 8 / 256, 256>>>(hidden, hhp, 8388608 / 8);
    f32_to_f16_kernel<<<4194304 / 8 / 256, 256>>>(in_proj_w, w1hp, 4194304 / 8);
    f32_to_f16_kernel<<<2097152 / 8 / 256, 256>>>(out_proj_w, wohp, 2097152 / 8);

    // 1) xz = in_proj (fp16 NT)
    {
        dim3 grid(LSEQ / 128, E2 / 128, 4);
        hgemm_nt<<<grid, 256, HSMEM>>>(w1hp, hhp, xzp, E2, LSEQ, DM,
                                       0LL, (long long)LSEQ * DM, (long long)E2 * LSEQ);
    }
    // 2) FFT features (8-warp blocks, wq split across warps)
    {
        dim3 grid(DI / 32, 32);
        fft_feat_kernel<<<grid, 256>>>(xzp, featp);
    }
    // 3) loss -> out[last]
    loss_kernel<<<1, 256>>>(featp, out, (long long)out_size - 1);
    // 4) A prep
    aprep_kernel<<<1, 256>>>(featp, A_log, Ap);
    // 5) conv + silu
    conv_kernel<<<4 * DI, 256>>>(xzp, conv_w, conv_b, xcp);
    // 6) x_dbl (tf32 NN)
    {
        dim3 grid(LSEQ / 128, 1, 4);
        tc_gemm_nn<0><<<grid, 256, SMEM_NN>>>(x_proj_w, xcp, xdblp, 96, LSEQ, DI,
                                              0LL, (long long)DI * LSEQ, (long long)96 * LSEQ,
                                              (const float*)0);
    }
    // 7) delta (tf32 NN + softplus/bias)
    {
        dim3 grid(LSEQ / 128, DI / 128, 4);
        tc_gemm_nn<1><<<grid, 256, SMEM_NN>>>(dt_proj_w, xdblp, deltap, DI, LSEQ, 64,
                                              0LL, (long long)96 * LSEQ, (long long)DI * LSEQ,
                                              dt_proj_b);
    }
    // 8) scan -> y fp16 (l,d)
    {
        dim3 grid(DI / 16, 4);
        scan_kernel<<<grid, 256>>>(deltap, xcp, xzp, xdblp, Ap, Dparam, yhp);
    }
    // 9) out = y @ out_proj^T (fp16 NT)
    {
        dim3 grid(DM / 128, LSEQ / 128, 4);
        hgemm_nt<<<grid, 256, HSMEM>>>(yhp, wohp, out, LSEQ, DM, DI,
                                       (long long)LSEQ * DI, 0LL, (long long)LSEQ * DM);
    }
}

// round 17
// speedup vs baseline: 1.1498x; 1.0336x over previous
#include <cuda_runtime.h>
#include <cuda_bf16.h>
#include <cuda_fp16.h>
#include <math.h>
#include <stdint.h>

#define LSEQ 2048
#define DI   2048
#define DM   1024
#define E2   4096
#define NST  16
#define NBT  32

// ---------------- scratch ----------------
__device__ float  g_xz[33554432];    // [4][4096][2048]
__device__ float  g_xc[16777216];    // [4][2048][2048]
__device__ float  g_xdbl[786432];    // [4][96][2048]
__device__ float  g_delta[16777216]; // [4][2048][2048] (also: x_dbl split-K partials)
__device__ float  g_feat[65536];     // [32][2048]
__device__ float  g_A[32768];        // [2048][16]
__device__ __half g_hh[8388608];     // fp16 hidden
__device__ __half g_w1h[4194304];    // fp16 in_proj_w
__device__ __half g_woh[2097152];    // fp16 out_proj_w
__device__ __half g_yh[16777216];    // fp16 y (l,d)

__device__ __forceinline__ float softplus_f(float x) {
    return fmaxf(x, 0.f) + log1pf(expf(-fabsf(x)));
}

__device__ __forceinline__ uint32_t f2tf(float f) {
    uint32_t r;
    asm("cvt.rna.tf32.f32 %0, %1;" : "=r"(r) : "f"(f));
    return r;
}

__device__ __forceinline__ void mma_tf32(float c[4], const uint32_t a[4], const uint32_t b[2]) {
    asm volatile(
        "mma.sync.aligned.m16n8k8.row.col.f32.tf32.tf32.f32 "
        "{%0,%1,%2,%3}, {%4,%5,%6,%7}, {%8,%9}, {%0,%1,%2,%3};\n"
        : "+f"(c[0]), "+f"(c[1]), "+f"(c[2]), "+f"(c[3])
        : "r"(a[0]), "r"(a[1]), "r"(a[2]), "r"(a[3]), "r"(b[0]), "r"(b[1]));
}

__device__ __forceinline__ void mma_f16(float c[4], const uint32_t a[4], const uint32_t b[2]) {
    asm volatile(
        "mma.sync.aligned.m16n8k16.row.col.f32.f16.f16.f32 "
        "{%0,%1,%2,%3}, {%4,%5,%6,%7}, {%8,%9}, {%0,%1,%2,%3};\n"
        : "+f"(c[0]), "+f"(c[1]), "+f"(c[2]), "+f"(c[3])
        : "r"(a[0]), "r"(a[1]), "r"(a[2]), "r"(a[3]), "r"(b[0]), "r"(b[1]));
}

__device__ __forceinline__ void ldm_x4(uint32_t r[4], uint32_t addr) {
    asm volatile("ldmatrix.sync.aligned.m8n8.x4.shared.b16 {%0,%1,%2,%3}, [%4];"
        : "=r"(r[0]), "=r"(r[1]), "=r"(r[2]), "=r"(r[3]) : "r"(addr));
}

__device__ __forceinline__ void cp_async16(uint32_t smem_addr, const void* gptr) {
    asm volatile("cp.async.cg.shared.global [%0], [%1], 16;\n" :: "r"(smem_addr), "l"(gptr));
}
__device__ __forceinline__ void cp_commit() {
    asm volatile("cp.async.commit_group;\n");
}
template<int N>
__device__ __forceinline__ void cp_wait() {
    asm volatile("cp.async.wait_group %0;\n" :: "n"(N));
}

__device__ __forceinline__ float blockReduceSum256(float v, float* red, int tid) {
    #pragma unroll
    for (int o = 16; o > 0; o >>= 1) v += __shfl_xor_sync(0xffffffffu, v, o);
    if ((tid & 31) == 0) red[tid >> 5] = v;
    __syncthreads();
    if (tid < 8) {
        float r = red[tid];
        #pragma unroll
        for (int o = 4; o > 0; o >>= 1) r += __shfl_xor_sync(0xffu, r, o);
        if (tid == 0) red[32] = r;
    }
    __syncthreads();
    float out = red[32];
    __syncthreads();
    return out;
}

__device__ __forceinline__ float blockReduceMax256(float v, float* red, int tid) {
    #pragma unroll
    for (int o = 16; o > 0; o >>= 1) v = fmaxf(v, __shfl_xor_sync(0xffffffffu, v, o));
    if ((tid & 31) == 0) red[tid >> 5] = v;
    __syncthreads();
    if (tid < 8) {
        float r = red[tid];
        #pragma unroll
        for (int o = 4; o > 0; o >>= 1) r = fmaxf(r, __shfl_xor_sync(0xffu, r, o));
        if (tid == 0) red[32] = r;
    }
    __syncthreads();
    float out = red[32];
    __syncthreads();
    return out;
}

// ---------------- f32 -> f16 conversion ----------------
__global__ void __launch_bounds__(256) f32_to_f16_kernel(const float* __restrict__ in,
                                                         __half* __restrict__ out, int n8) {
    int i = blockIdx.x * 256 + threadIdx.x;
    if (i < n8) {
        float4 a = ((const float4*)in)[2 * i];
        float4 b = ((const float4*)in)[2 * i + 1];
        __half2 h0 = __floats2half2_rn(a.x, a.y);
        __half2 h1 = __floats2half2_rn(a.z, a.w);
        __half2 h2 = __floats2half2_rn(b.x, b.y);
        __half2 h3 = __floats2half2_rn(b.z, b.w);
        uint4 r;
        r.x = *(uint32_t*)&h0; r.y = *(uint32_t*)&h1;
        r.z = *(uint32_t*)&h2; r.w = *(uint32_t*)&h3;
        ((uint4*)out)[i] = r;
    }
}

// =====================================================================
// FP16 NT GEMM (mma.sync): C[M,N]=A(MxK)*B(NxK)^T, fp32 accum.
// =====================================================================
#define HPITCH 72
#define HTSZ (128 * HPITCH)
#define HSTAGES 3

__global__ void __launch_bounds__(256, 2) hgemm_nt(const __half* __restrict__ Ag,
                                                   const __half* __restrict__ Bg,
                                                   float* __restrict__ Cg,
                                                   int M, int N, int K,
                                                   long long sA, long long sB, long long sC) {
    extern __shared__ __half hsm[];
    const __half* A = Ag + (long long)blockIdx.z * sA;
    const __half* B = Bg + (long long)blockIdx.z * sB;
    float*        C = Cg + (long long)blockIdx.z * sC;
    const int m0 = blockIdx.y * 128, n0 = blockIdx.x * 128;

    const int tid = threadIdx.x;
    const int wid = tid >> 5, lane = tid & 31;
    const int wm = (wid >> 2) * 64;
    const int wn = (wid & 3) * 32;
    const int g = lane >> 2, tg = lane & 3;
    const int r8 = lane & 7, q = lane >> 3;

    const int nk = K >> 6;

    auto issue_tile = [&](int s, int kt) {
        if (kt < nk) {
            int k0 = kt << 6;
            __half* As = hsm + s * 2 * HTSZ;
            __half* Bs = As + HTSZ;
            #pragma unroll
            for (int r = 0; r < 4; r++) {
                int c = tid + r * 256;
                int row = c >> 3;
                int kq = (c & 7) << 3;
                uint32_t dst = (uint32_t)__cvta_generic_to_shared(As + row * HPITCH + kq);
                cp_async16(dst, A + (long long)(m0 + row) * K + k0 + kq);
            }
            #pragma unroll
            for (int r = 0; r < 4; r++) {
                int c = tid + r * 256;
                int row = c >> 3;
                int kq = (c & 7) << 3;
                uint32_t dst = (uint32_t)__cvta_generic_to_shared(Bs + row * HPITCH + kq);
                cp_async16(dst, B + (long long)(n0 + row) * K + k0 + kq);
            }
        }
        cp_commit();
    };

    float c[4][4][4];
    #pragma unroll
    for (int mi = 0; mi < 4; mi++)
        #pragma unroll
        for (int ni = 0; ni < 4; ni++)
            #pragma unroll
            for (int r = 0; r < 4; r++) c[mi][ni][r] = 0.f;

    issue_tile(0, 0);
    issue_tile(1, 1);

    for (int kt = 0; kt < nk; kt++) {
        issue_tile((kt + 2) % HSTAGES, kt + 2);
        cp_wait<2>();
        __syncthreads();
        const __half* As = hsm + (kt % HSTAGES) * 2 * HTSZ;
        const __half* Bs = As + HTSZ;

        #pragma unroll
        for (int kk = 0; kk < 64; kk += 16) {
            uint32_t a[4][4], bfr[4][2];
            #pragma unroll
            for (int mi = 0; mi < 4; mi++) {
                const __half* ap = As + (wm + mi * 16 + ((q & 1) << 3) + r8) * HPITCH
                                      + kk + ((q >> 1) << 3);
                ldm_x4(a[mi], (uint32_t)__cvta_generic_to_shared(ap));
            }
            #pragma unroll
            for (int nn = 0; nn < 2; nn++) {
                uint32_t bt[4];
                const __half* bp = Bs + (wn + nn * 16 + ((q >> 1) << 3) + r8) * HPITCH
                                      + kk + ((q & 1) << 3);
                ldm_x4(bt, (uint32_t)__cvta_generic_to_shared(bp));
                bfr[2 * nn][0] = bt[0];     bfr[2 * nn][1] = bt[1];
                bfr[2 * nn + 1][0] = bt[2]; bfr[2 * nn + 1][1] = bt[3];
            }
            #pragma unroll
            for (int mi = 0; mi < 4; mi++)
                #pragma unroll
                for (int ni = 0; ni < 4; ni++)
                    mma_f16(c[mi][ni], a[mi], bfr[ni]);
        }
        __syncthreads();
    }

    #pragma unroll
    for (int mi = 0; mi < 4; mi++) {
        int r0 = m0 + wm + mi * 16 + g;
        int r1 = r0 + 8;
        #pragma unroll
        for (int ni = 0; ni < 4; ni++) {
            int col = n0 + wn + ni * 8 + 2 * tg;
            *(float2*)(C + (long long)r0 * N + col) = make_float2(c[mi][ni][0], c[mi][ni][1]);
            *(float2*)(C + (long long)r1 * N + col) = make_float2(c[mi][ni][2], c[mi][ni][3]);
        }
    }
}
#define HSMEM (HSTAGES * 2 * HTSZ * 2)

// =====================================================================
// TF32 NN GEMM: C[M,N]=A(MxK)*B(KxN); EPI=1: softplus(+bias)
// SPLITK=1: blockIdx.z encodes (ks = z>>2, b = z&3); K passed = split size.
// =====================================================================
#define APITCH 36
#define BPITCH_NN 136
#define ASZ (128 * APITCH)
#define BSZ_N (32 * BPITCH_NN)
#define STAGES 3

template<int EPI, int SPLITK>
__global__ void __launch_bounds__(256, 2) tc_gemm_nn(const float* __restrict__ Ag,
                                                     const float* __restrict__ Bg,
                                                     float* __restrict__ Cg,
                                                     int M, int N, int K,
                                                     long long sA, long long sB, long long sC,
                                                     const float* __restrict__ bias) {
    extern __shared__ float smem[];
    float* AsBase = smem;
    float* BsBase = smem + STAGES * ASZ;

    const float* A;
    const float* B;
    float*       C;
    if (SPLITK) {
        int ks = blockIdx.z >> 2, b = blockIdx.z & 3;
        A = Ag + (long long)ks * K;                              // A row stride = total K (sA)
        B = Bg + (long long)b * sB + (long long)ks * K * N;      // B rows offset by ks*K
        C = Cg + (long long)blockIdx.z * sC;                     // per-(ks,b) partial
    } else {
        A = Ag + (long long)blockIdx.z * sA;
        B = Bg + (long long)blockIdx.z * sB;
        C = Cg + (long long)blockIdx.z * sC;
    }
    const int m0 = blockIdx.y * 128, n0 = blockIdx.x * 128;
    const long long ldA = SPLITK ? sA : (long long)K;   // A leading dim (row stride in floats)

    const int tid = threadIdx.x;
    const int wid = tid >> 5, lane = tid & 31;
    const int wm = (wid >> 2) * 64;
    const int wn = (wid & 3) * 32;
    const int g = lane >> 2, tg = lane & 3;

    const int nk = K >> 5;

    auto issue_tile = [&](int s, int kt) {
        if (kt < nk) {
            int k0 = kt << 5;
            float* As = AsBase + s * ASZ;
            float* Bs = BsBase + s * BSZ_N;
            #pragma unroll
            for (int r = 0; r < 4; r++) {
                int c = tid + r * 256;
                int row = c >> 3;
                int kq = (c & 7) << 2;
                int mrow = m0 + row;
                if (mrow >= M) mrow = M - 1;
                uint32_t dst = (uint32_t)__cvta_generic_to_shared(As + row * APITCH + kq);
                cp_async16(dst, A + (long long)mrow * ldA + k0 + kq);
            }
            #pragma unroll
            for (int r = 0; r < 4; r++) {
                int c = tid + r * 256;
                int k = c >> 5;
                int nq = (c & 31) << 2;
                uint32_t dst = (uint32_t)__cvta_generic_to_shared(Bs + k * BPITCH_NN + nq);
                cp_async16(dst, B + (long long)(k0 + k) * N + n0 + nq);
            }
        }
        cp_commit();
    };

    float c[4][4][4];
    #pragma unroll
    for (int mi = 0; mi < 4; mi++)
        #pragma unroll
        for (int ni = 0; ni < 4; ni++)
            #pragma unroll
            for (int r = 0; r < 4; r++) c[mi][ni][r] = 0.f;

    issue_tile(0, 0);
    issue_tile(1, 1);

    for (int kt = 0; kt < nk; kt++) {
        issue_tile((kt + 2) % STAGES, kt + 2);
        cp_wait<2>();
        __syncthreads();
        const float* As = AsBase + (kt % STAGES) * ASZ;
        const float* Bs = BsBase + (kt % STAGES) * BSZ_N;

        #pragma unroll
        for (int kk = 0; kk < 32; kk += 8) {
            uint32_t a[4][4], bfr[4][2];
            #pragma unroll
            for (int mi = 0; mi < 4; mi++) {
                const float* Ar = As + (wm + mi * 16 + g) * APITCH + kk + tg;
                a[mi][0] = f2tf(Ar[0]);
                a[mi][1] = f2tf(Ar[8 * APITCH]);
                a[mi][2] = f2tf(Ar[4]);
                a[mi][3] = f2tf(Ar[8 * APITCH + 4]);
            }
            #pragma unroll
            for (int ni = 0; ni < 4; ni++) {
                const float* Br = Bs + (kk + tg) * BPITCH_NN + wn + ni * 8 + g;
                bfr[ni][0] = f2tf(Br[0]);
                bfr[ni][1] = f2tf(Br[4 * BPITCH_NN]);
            }
            #pragma unroll
            for (int mi = 0; mi < 4; mi++)
                #pragma unroll
                for (int ni = 0; ni < 4; ni++)
                    mma_tf32(c[mi][ni], a[mi], bfr[ni]);
        }
        __syncthreads();
    }

    #pragma unroll
    for (int mi = 0; mi < 4; mi++) {
        int r0 = m0 + wm + mi * 16 + g;
        int r1 = r0 + 8;
        float b0v = 0.f, b1v = 0.f;
        if (EPI) {
            if (r0 < M) b0v = bias[r0];
            if (r1 < M) b1v = bias[r1];
        }
        #pragma unroll
        for (int ni = 0; ni < 4; ni++) {
            int col = n0 + wn + ni * 8 + 2 * tg;
            float v0 = c[mi][ni][0], v1 = c[mi][ni][1];
            float v2 = c[mi][ni][2], v3 = c[mi][ni][3];
            if (EPI) {
                v0 = softplus_f(v0 + b0v); v1 = softplus_f(v1 + b0v);
                v2 = softplus_f(v2 + b1v); v3 = softplus_f(v3 + b1v);
            }
            if (r0 < M) *(float2*)(C + (long long)r0 * N + col) = make_float2(v0, v1);
            if (r1 < M) *(float2*)(C + (long long)r1 * N + col) = make_float2(v2, v3);
        }
    }
}
#define SMEM_NN ((STAGES * (ASZ + BSZ_N)) * 4)

// ---------------- x_dbl split-K reduction: xdbl[b] = sum_ks part[ks*4+b] ----------
__global__ void __launch_bounds__(256) xdbl_reduce_kernel(const float* __restrict__ part,
                                                          float* __restrict__ out) {
    const int PER_B = 96 * LSEQ / 4;    // float4s per batch slice = 49152
    int idx = blockIdx.x * 256 + threadIdx.x;       // 0..196607
    int b = idx / PER_B, r = idx - b * PER_B;
    const float4* p = (const float4*)part;
    float4 acc = p[(long long)(0 * 4 + b) * PER_B + r];
    #pragma unroll
    for (int ks = 1; ks < 4; ks++) {
        float4 v = p[(long long)(ks * 4 + b) * PER_B + r];
        acc.x += v.x; acc.y += v.y; acc.z += v.z; acc.w += v.w;
    }
    ((float4*)out)[(long long)b * PER_B + r] = acc;
}

// ---------------- FFT channel-alignment features (8-warp blocks) ----------------
__global__ void __launch_bounds__(256) fft_feat_kernel(const float* __restrict__ xz,
                                                       float* __restrict__ feat) {
    __shared__ float sx[256 * 33];
    __shared__ float twc[16], tws[16];
    __shared__ float sTot[8][32], sHigh[8][32];
    int tid = threadIdx.x;
    int lane = tid & 31, w = tid >> 5;
    int bt = blockIdx.y;
    int b = bt >> 3, t = bt & 7;
    int c0 = blockIdx.x * 32;
    if (tid < 16) {
        float ang = tid * 0.39269908169872414f;
        twc[tid] = cosf(ang);
        tws[tid] = sinf(ang);
    }
    const float* xb = xz + ((long long)(b * E2 + c0)) * LSEQ + t * 256;
    for (int i = tid; i < 32 * 256; i += 256) {
        int c = i >> 8, l = i & 255;
        sx[l * 33 + c] = xb[(long long)c * LSEQ + l];
    }
    __syncthreads();
    int c = lane;
    float S_tot = 0.f, S_high = 0.f;
    for (int wq = w; wq < 9; wq += 8) {
        float Rr[16], Ri[16];
        #pragma unroll
        for (int h = 0; h < 16; h++) {
            float rr = 0.f, ri = 0.f;
            #pragma unroll
            for (int ww = 0; ww < 16; ww++) {
                float v = sx[(h * 16 + ww) * 33 + c];
                int id = (ww * wq) & 15;
                rr += v * twc[id];
                ri -= v * tws[id];
            }
            Rr[h] = rr; Ri[h] = ri;
        }
        #pragma unroll
        for (int hq = 0; hq < 16; hq++) {
            float fre = 0.f, fim = 0.f;
            #pragma unroll
            for (int h = 0; h < 16; h++) {
                int id = (h * hq) & 15;
                float cc2 = twc[id], sn = tws[id];
                fre += Rr[h] * cc2 + Ri[h] * sn;
                fim += Ri[h] * cc2 - Rr[h] * sn;
            }
            float mag = sqrtf(fre * fre + fim * fim + 1e-8f);
            S_tot += mag;
            int hs = (hq + 8) & 15;
            int ws = wq + 4; if (ws >= 9) ws -= 9;
            float dh = (hs - 8) * (1.0f / 16.0f);
            float dw = (ws - 4) * (1.0f / 9.0f);
            if (dh * dh + dw * dw >= 0.25f) S_high += mag;
        }
    }
    sTot[w][lane] = S_tot;
    sHigh[w][lane] = S_high;
    __syncthreads();
    if (tid < 32) {
        float st = 0.f, sh = 0.f;
        #pragma unroll
        for (int ww = 0; ww < 8; ww++) { st += sTot[ww][tid]; sh += sHigh[ww][tid]; }
        feat[(long long)bt * DI + c0 + tid] = sh / (st + 1e-8f);
    }
}

// ---------------- fused loss + aprep (block 0 = loss, block 1 = aprep) ----------
__global__ void __launch_bounds__(256) loss_aprep_kernel(const float* __restrict__ feat,
                                                         const float* __restrict__ A_log,
                                                         float* __restrict__ Aout,
                                                         float* __restrict__ out,
                                                         long long loss_idx) {
    __shared__ float sf[DI];
    __shared__ float satt[DI];
    __shared__ float red[40];
    __shared__ float wmx[8][16], wmn[8][16];
    __shared__ float colMx[16], colMn[16];
    __shared__ float inv[NBT];
    int tid = threadIdx.x;
    int lane = tid & 31, wid = tid >> 5;

    if (blockIdx.x == 0) {
        // ---- loss ----
        for (int i = wid; i < NBT; i += 8) {
            float ss = 0.f;
            for (int cc = lane; cc < DI; cc += 32) {
                float v = feat[i * DI + cc];
                ss += v * v;
            }
            #pragma unroll
            for (int o = 16; o > 0; o >>= 1) ss += __shfl_xor_sync(0xffffffffu, ss, o);
            if (lane == 0) inv[i] = 1.f / fmaxf(sqrtf(ss), 1e-12f);
        }
        __syncthreads();
        float tt = 0.f;
        for (int cc = tid; cc < DI; cc += 256) {
            float gsum = 0.f;
            #pragma unroll
            for (int i = 0; i < NBT; i++) gsum += feat[i * DI + cc] * inv[i];
            tt += gsum * gsum;
        }
        tt = blockReduceSum256(tt, red, tid);
        if (tid == 0) out[loss_idx] = 1.f - tt / (float)(NBT * NBT);
    } else {
        // ---- aprep ----
        for (int cc = tid; cc < DI; cc += 256) {
            float s = 0.f;
            for (int i = 0; i < NBT; i++) s += feat[i * DI + cc];
            sf[cc] = s * (1.0f / NBT);
        }
        __syncthreads();
        float mx = -3.4e38f;
        for (int cc = tid; cc < DI; cc += 256) mx = fmaxf(mx, sf[cc]);
        mx = blockReduceMax256(mx, red, tid);
        float se = 0.f;
        for (int cc = tid; cc < DI; cc += 256) {
            float e = expf(sf[cc] - mx);
            sf[cc] = e;
            se += e;
        }
        se = blockReduceSum256(se, red, tid);
        float inv_se = 1.f / se;
        float cm[16], cn[16];
        #pragma unroll
        for (int n = 0; n < 16; n++) { cm[n] = -3.4e38f; cn[n] = 3.4e38f; }
        float am = 0.f;
        for (int d = tid; d < DI; d += 256) {
            float ss = 0.f;
            #pragma unroll
            for (int n = 0; n < 16; n++) {
                float al = A_log[d * 16 + n];
                float e = expf(al);
                ss += e * e;
                cm[n] = fmaxf(cm[n], al);
                cn[n] = fminf(cn[n], al);
            }
            float an = sqrtf(ss);
            satt[d] = an;
            am = fmaxf(am, an);
        }
        am = blockReduceMax256(am, red, tid);
        #pragma unroll
        for (int o = 16; o > 0; o >>= 1) {
            #pragma unroll
            for (int n = 0; n < 16; n++) {
                cm[n] = fmaxf(cm[n], __shfl_xor_sync(0xffffffffu, cm[n], o));
                cn[n] = fminf(cn[n], __shfl_xor_sync(0xffffffffu, cn[n], o));
            }
        }
        if (lane == 0) {
            #pragma unroll
            for (int n = 0; n < 16; n++) { wmx[wid][n] = cm[n]; wmn[wid][n] = cn[n]; }
        }
        __syncthreads();
        if (tid < 16) {
            float m = -3.4e38f, mn = 3.4e38f;
            for (int w = 0; w < 8; w++) { m = fmaxf(m, wmx[w][tid]); mn = fminf(mn, wmn[w][tid]); }
            colMx[tid] = m; colMn[tid] = mn;
        }
        __syncthreads();
        float inv_am = 1.f / (am + 1e-8f);
        for (int i = tid; i < DI * 16; i += 256) {
            int d = i >> 4, n = i & 15;
            float f = sf[d] * inv_se;
            float att = satt[d] * inv_am;
            float alpha = fminf(fmaxf(f * (1.f - att), 0.f), 1.f);
            float al = A_log[i];
            float fl = colMx[n] + colMn[n] - al;
            float an = (1.f - alpha) * al + alpha * fl;
            Aout[i] = -expf(an);
        }
    }
}

// ---------------- causal depthwise conv (width 4) + silu, vectorized ----------------
__global__ void __launch_bounds__(256) conv_kernel(const float* __restrict__ xz,
                                                   const float* __restrict__ cw,
                                                   const float* __restrict__ cb,
                                                   float* __restrict__ xc) {
    __shared__ float row[LSEQ + 8];
    int rid = blockIdx.x;
    int b = rid >> 11, d = rid & 2047;
    int tid = threadIdx.x;
    const float* xp = xz + ((long long)b * E2 + d) * LSEQ;
    if (tid < 4) row[tid] = 0.f;
    #pragma unroll
    for (int it = 0; it < 2; it++) {
        int i = tid + it * 256;
        *(float4*)&row[4 + i * 4] = ((const float4*)xp)[i];
    }
    __syncthreads();
    float w0 = cw[d * 4 + 0], w1 = cw[d * 4 + 1], w2 = cw[d * 4 + 2], w3 = cw[d * 4 + 3];
    float bb = cb[d];
    float* op = xc + ((long long)b * DI + d) * LSEQ;
    #pragma unroll
    for (int it = 0; it < 2; it++) {
        int l = (tid + it * 256) * 4;
        float4 o;
        #pragma unroll
        for (int s = 0; s < 4; s++) {
            float v = bb + w0 * row[l + s + 1] + w1 * row[l + s + 2]
                         + w2 * row[l + s + 3] + w3 * row[l + s + 4];
            ((float*)&o)[s] = v / (1.f + __expf(-v));
        }
        *(float4*)(op + l) = o;
    }
}

// ---------------- selective scan ----------------
__global__ void __launch_bounds__(256) scan_kernel(const float* __restrict__ delta,
                                                   const float* __restrict__ xc,
                                                   const float* __restrict__ xz,
                                                   const float* __restrict__ xdbl,
                                                   const float* __restrict__ A,
                                                   const float* __restrict__ Dp,
                                                   __half* __restrict__ y) {
    __shared__ float sDel[64][17], sU[64][17], sZ[64][17];
    __shared__ float sB[64][17], sC[64][17], sY[64][17];
    int tid = threadIdx.x;
    int ci = tid >> 4, n = tid & 15;
    int b = blockIdx.y;
    int d0 = blockIdx.x * 16;
    int d = d0 + ci;
    const float* delp = delta + ((long long)b * DI + d0) * LSEQ;
    const float* up   = xc    + ((long long)b * DI + d0) * LSEQ;
    const float* zp   = xz    + ((long long)b * E2 + DI + d0) * LSEQ;
    const float* bp   = xdbl  + ((long long)b * 96 + 64) * LSEQ;
    const float* cp   = xdbl  + ((long long)b * 96 + 80) * LSEQ;
    __half*      yp   = y     + (long long)b * LSEQ * DI;
    float a = A[d * 16 + n];
    float dD = Dp[d];
    float s = 0.f;
    const int scc = tid >> 4;
    const int sjq = (tid & 15) << 2;
    for (int l0 = 0; l0 < LSEQ; l0 += 64) {
        {
            long long off = (long long)scc * LSEQ + l0 + sjq;
            float4 vD = *(const float4*)(delp + off);
            float4 vU = *(const float4*)(up + off);
            float4 vZ = *(const float4*)(zp + off);
            float4 vB = *(const float4*)(bp + off);
            float4 vC = *(const float4*)(cp + off);
            sDel[sjq + 0][scc] = vD.x; sDel[sjq + 1][scc] = vD.y;
            sDel[sjq + 2][scc] = vD.z; sDel[sjq + 3][scc] = vD.w;
            sU[sjq + 0][scc] = vU.x; sU[sjq + 1][scc] = vU.y;
            sU[sjq + 2][scc] = vU.z; sU[sjq + 3][scc] = vU.w;
            sZ[sjq + 0][scc] = vZ.x; sZ[sjq + 1][scc] = vZ.y;
            sZ[sjq + 2][scc] = vZ.z; sZ[sjq + 3][scc] = vZ.w;
            sB[sjq + 0][scc] = vB.x; sB[sjq + 1][scc] = vB.y;
            sB[sjq + 2][scc] = vB.z; sB[sjq + 3][scc] = vB.w;
            sC[sjq + 0][scc] = vC.x; sC[sjq + 1][scc] = vC.y;
            sC[sjq + 2][scc] = vC.z; sC[sjq + 3][scc] = vC.w;
        }
        __syncthreads();
        #pragma unroll 4
        for (int j = 0; j < 64; j++) {
            float dl = sDel[j][ci];
            float u  = sU[j][ci];
            float bb = sB[j][n];
            float ccv = sC[j][n];
            s = s * __expf(dl * a) + (dl * u) * bb;
            float p = s * ccv;
            #pragma unroll
            for (int o = 8; o > 0; o >>= 1) p += __shfl_xor_sync(0xffffffffu, p, o, 16);
            if (n == 0) {
                float z = sZ[j][ci];
                sY[j][ci] = (p + u * dD) * (z / (1.f + __expf(-z)));
            }
        }
        __syncthreads();
        if (tid < 128) {
            int j = tid >> 1;
            int c8 = (tid & 1) << 3;
            const float* yr = &sY[j][c8];
            __half2 h0 = __floats2half2_rn(yr[0], yr[1]);
            __half2 h1 = __floats2half2_rn(yr[2], yr[3]);
            __half2 h2 = __floats2half2_rn(yr[4], yr[5]);
            __half2 h3 = __floats2half2_rn(yr[6], yr[7]);
            uint4 r;
            r.x = *(uint32_t*)&h0; r.y = *(uint32_t*)&h1;
            r.z = *(uint32_t*)&h2; r.w = *(uint32_t*)&h3;
            *(uint4*)(yp + (long long)(l0 + j) * DI + d0 + c8) = r;
        }
        __syncthreads();
    }
}

// ---------------- launch ----------------
extern "C" void kernel_launch(void* const* d_in, const int* in_sizes, int n_in,
                              void* d_out, int out_size) {
    const float* hidden    = (const float*)d_in[0];
    const float* in_proj_w = (const float*)d_in[4];
    const float* conv_w    = (const float*)d_in[5];
    const float* conv_b    = (const float*)d_in[6];
    const float* x_proj_w  = (const float*)d_in[7];
    const float* dt_proj_w = (const float*)d_in[8];
    const float* dt_proj_b = (const float*)d_in[9];
    const float* A_log     = (const float*)d_in[10];
    const float* Dparam    = (const float*)d_in[11];
    const float* out_proj_w= (const float*)d_in[12];
    float* out = (float*)d_out;

    float *xzp, *xcp, *xdblp, *deltap, *featp, *Ap;
    __half *hhp, *w1hp, *wohp, *yhp;
    cudaGetSymbolAddress((void**)&xzp, g_xz);
    cudaGetSymbolAddress((void**)&xcp, g_xc);
    cudaGetSymbolAddress((void**)&xdblp, g_xdbl);
    cudaGetSymbolAddress((void**)&deltap, g_delta);
    cudaGetSymbolAddress((void**)&featp, g_feat);
    cudaGetSymbolAddress((void**)&Ap, g_A);
    cudaGetSymbolAddress((void**)&hhp, g_hh);
    cudaGetSymbolAddress((void**)&w1hp, g_w1h);
    cudaGetSymbolAddress((void**)&wohp, g_woh);
    cudaGetSymbolAddress((void**)&yhp, g_yh);

    cudaFuncSetAttribute(hgemm_nt, cudaFuncAttributeMaxDynamicSharedMemorySize, HSMEM);
    cudaFuncSetAttribute(tc_gemm_nn<0, 1>, cudaFuncAttributeMaxDynamicSharedMemorySize, SMEM_NN);
    cudaFuncSetAttribute(tc_gemm_nn<1, 0>, cudaFuncAttributeMaxDynamicSharedMemorySize, SMEM_NN);

    // 0) convert big-GEMM operands to fp16
    f32_to_f16_kernel<<<8388608 / 8 / 256, 256>>>(hidden, hhp, 8388608 / 8);
    f32_to_f16_kernel<<<4194304 / 8 / 256, 256>>>(in_proj_w, w1hp, 4194304 / 8);
    f32_to_f16_kernel<<<2097152 / 8 / 256, 256>>>(out_proj_w, wohp, 2097152 / 8);

    // 1) xz = in_proj (fp16 NT)
    {
        dim3 grid(LSEQ / 128, E2 / 128, 4);
        hgemm_nt<<<grid, 256, HSMEM>>>(w1hp, hhp, xzp, E2, LSEQ, DM,
                                       0LL, (long long)LSEQ * DM, (long long)E2 * LSEQ);
    }
    // 2) FFT features
    {
        dim3 grid(DI / 32, 32);
        fft_feat_kernel<<<grid, 256>>>(xzp, featp);
    }
    // 3) fused loss + aprep (2 blocks, run concurrently)
    loss_aprep_kernel<<<2, 256>>>(featp, A_log, Ap, out, (long long)out_size - 1);
    // 4) conv + silu
    conv_kernel<<<4 * DI, 256>>>(xzp, conv_w, conv_b, xcp);
    // 5) x_dbl split-K x4: partials into g_delta, then reduce into g_xdbl
    {
        dim3 grid(LSEQ / 128, 1, 16);   // z = ks*4 + b
        tc_gemm_nn<0, 1><<<grid, 256, SMEM_NN>>>(x_proj_w, xcp, deltap, 96, LSEQ, DI / 4,
                                                 (long long)DI,            // sA = total K (ldA)
                                                 (long long)DI * LSEQ,     // sB = batch stride
                                                 (long long)96 * LSEQ,     // sC = partial stride
                                                 (const float*)0);
        xdbl_reduce_kernel<<<(4 * 96 * LSEQ / 4) / 256, 256>>>(deltap, xdblp);
    }
    // 6) delta (tf32 NN + softplus/bias)
    {
        dim3 grid(LSEQ / 128, DI / 128, 4);
        tc_gemm_nn<1, 0><<<grid, 256, SMEM_NN>>>(dt_proj_w, xdblp, deltap, DI, LSEQ, 64,
                                                 0LL, (long long)96 * LSEQ, (long long)DI * LSEQ,
                                                 dt_proj_b);
    }
    // 7) scan -> y fp16 (l,d)
    {
        dim3 grid(DI / 16, 4);
        scan_kernel<<<grid, 256>>>(deltap, xcp, xzp, xdblp, Ap, Dparam, yhp);
    }
    // 8) out = y @ out_proj^T (fp16 NT)
    {
        dim3 grid(DM / 128, LSEQ / 128, 4);
        hgemm_nt<<<grid, 256, HSMEM>>>(yhp, wohp, out, LSEQ, DM, DI,
                                       (long long)LSEQ * DI, 0LL, (long long)LSEQ * DM);
    }
}